// round 1
// baseline (speedup 1.0000x reference)
#include <cuda_runtime.h>
#include <math.h>

#define BB 4
#define TT 2048
#define DD 1024
#define HH 16
#define DKK 64
#define NTOK (BB*TT)      // 8192
#define D3 (3*DD)         // 3072

// Scratch (allocation-free rule: __device__ globals)
__device__ float g_qkv[NTOK * D3];   // 96 MB
__device__ float g_att[NTOK * DD];   // 32 MB
__device__ float g_res[NTOK * DD];   // 32 MB

// ---------------------------------------------------------------------------
// Generic SGEMM: C[M,N] = A[M,K] @ B[K,N] + bias[N] (+ res[M,N] if ADD_RES)
// 128x128 tile, BK=8, 256 threads, 8x8 per-thread microtile.
// M,N multiples of 128; K multiple of 8.
// ---------------------------------------------------------------------------
template<bool ADD_RES>
__global__ __launch_bounds__(256)
void sgemm_kernel(const float* __restrict__ A, const float* __restrict__ Bm,
                  const float* __restrict__ bias, const float* __restrict__ res,
                  float* __restrict__ C, int M, int N, int K)
{
    __shared__ float As[8][128];
    __shared__ float Bs[8][128];

    const int tid = threadIdx.x;
    const int tx = tid & 15;
    const int ty = tid >> 4;
    const int row0 = blockIdx.y * 128;
    const int col0 = blockIdx.x * 128;

    float acc[8][8];
#pragma unroll
    for (int i = 0; i < 8; i++)
#pragma unroll
        for (int j = 0; j < 8; j++) acc[i][j] = 0.f;

    const int aRow = tid >> 1;
    const int aCol = (tid & 1) * 4;
    const int bRow = tid >> 5;
    const int bCol = (tid & 31) * 4;

    const float* Ag = A + (size_t)(row0 + aRow) * K + aCol;
    const float* Bg = Bm + (size_t)bRow * N + col0 + bCol;

    for (int k0 = 0; k0 < K; k0 += 8) {
        float4 av = *(const float4*)(Ag + k0);
        float4 bv = *(const float4*)(Bg + (size_t)k0 * N);
        As[aCol + 0][aRow] = av.x;
        As[aCol + 1][aRow] = av.y;
        As[aCol + 2][aRow] = av.z;
        As[aCol + 3][aRow] = av.w;
        *(float4*)&Bs[bRow][bCol] = bv;
        __syncthreads();
#pragma unroll
        for (int k = 0; k < 8; k++) {
            float ar[8], br[8];
            *(float4*)&ar[0] = *(const float4*)&As[k][ty * 8];
            *(float4*)&ar[4] = *(const float4*)&As[k][ty * 8 + 4];
            *(float4*)&br[0] = *(const float4*)&Bs[k][tx * 8];
            *(float4*)&br[4] = *(const float4*)&Bs[k][tx * 8 + 4];
#pragma unroll
            for (int i = 0; i < 8; i++)
#pragma unroll
                for (int j = 0; j < 8; j++)
                    acc[i][j] += ar[i] * br[j];
        }
        __syncthreads();
    }

#pragma unroll
    for (int i = 0; i < 8; i++) {
        const int r = row0 + ty * 8 + i;
#pragma unroll
        for (int j = 0; j < 8; j += 4) {
            const int c = col0 + tx * 8 + j;
            float4 o;
            o.x = acc[i][j + 0] + bias[c + 0];
            o.y = acc[i][j + 1] + bias[c + 1];
            o.z = acc[i][j + 2] + bias[c + 2];
            o.w = acc[i][j + 3] + bias[c + 3];
            if (ADD_RES) {
                const float4 rv = *(const float4*)(res + (size_t)r * N + c);
                o.x += rv.x; o.y += rv.y; o.z += rv.z; o.w += rv.w;
            }
            *(float4*)(C + (size_t)r * N + c) = o;
        }
    }
}

// ---------------------------------------------------------------------------
// Flash-attention fp32: per (b,h), 64-query tile x 64-key tiles, dk=64.
// qkv layout: [NTOK, 3072]; q at +0, k at +1024, v at +2048, head h at +h*64.
// Output written to g_att as [B,T,D] (i.e. [b*T+t, h*64+d]).
// Dynamic smem: Qs^T + Ks^T + Vs + Ps = 4 * 64*64 floats = 64 KB.
// ---------------------------------------------------------------------------
__global__ __launch_bounds__(256)
void attn_kernel(const float* __restrict__ qkv, float* __restrict__ out)
{
    extern __shared__ float sh[];
    float* Qs = sh;             // [d][m]  (transposed)
    float* Ks = sh + 4096;      // [d][n]  (transposed)
    float* Vs = sh + 8192;      // [n][d]  (row-major)
    float* Ps = sh + 12288;     // [n][m]  (P transposed)

    const int tid = threadIdx.x;
    const int tx = tid & 15;
    const int ty = tid >> 4;
    const int q0 = blockIdx.x * 64;
    const int bh = blockIdx.y;
    const int b  = bh >> 4;
    const int h  = bh & 15;

    const float* base = qkv + (size_t)(b * TT) * D3 + h * DKK;

    // Load Q tile transposed: Qs[d*64 + m]
#pragma unroll
    for (int it = 0; it < 4; it++) {
        const int idx = tid + it * 256;     // 0..1023
        const int r  = idx >> 4;            // query row 0..63
        const int cg = (idx & 15) * 4;      // dk col group
        float4 v = *(const float4*)(base + (size_t)(q0 + r) * D3 + cg);
        Qs[(cg + 0) * 64 + r] = v.x;
        Qs[(cg + 1) * 64 + r] = v.y;
        Qs[(cg + 2) * 64 + r] = v.z;
        Qs[(cg + 3) * 64 + r] = v.w;
    }

    float acc[4][4];
#pragma unroll
    for (int i = 0; i < 4; i++)
#pragma unroll
        for (int j = 0; j < 4; j++) acc[i][j] = 0.f;
    float mrow[4], lrow[4];
#pragma unroll
    for (int i = 0; i < 4; i++) { mrow[i] = -1e30f; lrow[i] = 0.f; }

    for (int kt = 0; kt < TT / 64; kt++) {
        __syncthreads();  // prior P·V reads done (and Q visible, first iter)

        // Load K tile transposed + V tile row-major
#pragma unroll
        for (int it = 0; it < 4; it++) {
            const int idx = tid + it * 256;
            const int r  = idx >> 4;
            const int cg = (idx & 15) * 4;
            const size_t trow = (size_t)(kt * 64 + r) * D3;
            float4 kv = *(const float4*)(base + DD + trow + cg);
            Ks[(cg + 0) * 64 + r] = kv.x;
            Ks[(cg + 1) * 64 + r] = kv.y;
            Ks[(cg + 2) * 64 + r] = kv.z;
            Ks[(cg + 3) * 64 + r] = kv.w;
            *(float4*)&Vs[r * 64 + cg] = *(const float4*)(base + 2 * DD + trow + cg);
        }
        __syncthreads();

        // S[i][j] = sum_d Q[m=ty*4+i][d] * K[n=tx*4+j][d], scaled by 1/8
        float s[4][4];
#pragma unroll
        for (int i = 0; i < 4; i++)
#pragma unroll
            for (int j = 0; j < 4; j++) s[i][j] = 0.f;
#pragma unroll 8
        for (int d = 0; d < 64; d++) {
            const float4 qv = *(const float4*)&Qs[d * 64 + ty * 4];
            const float4 kv = *(const float4*)&Ks[d * 64 + tx * 4];
            const float qr[4] = {qv.x, qv.y, qv.z, qv.w};
            const float kr[4] = {kv.x, kv.y, kv.z, kv.w};
#pragma unroll
            for (int i = 0; i < 4; i++)
#pragma unroll
                for (int j = 0; j < 4; j++)
                    s[i][j] += qr[i] * kr[j];
        }
#pragma unroll
        for (int i = 0; i < 4; i++)
#pragma unroll
            for (int j = 0; j < 4; j++) s[i][j] *= 0.125f;

        // Online softmax per query row (16-lane segmented reductions)
        float mnew[4], alpha[4], rsum[4];
#pragma unroll
        for (int i = 0; i < 4; i++) {
            float mx = fmaxf(fmaxf(s[i][0], s[i][1]), fmaxf(s[i][2], s[i][3]));
#pragma unroll
            for (int off = 8; off >= 1; off >>= 1)
                mx = fmaxf(mx, __shfl_xor_sync(0xffffffffu, mx, off));
            mnew[i]  = fmaxf(mrow[i], mx);
            alpha[i] = __expf(mrow[i] - mnew[i]);
            float su = 0.f;
#pragma unroll
            for (int j = 0; j < 4; j++) {
                s[i][j] = __expf(s[i][j] - mnew[i]);
                su += s[i][j];
            }
#pragma unroll
            for (int off = 8; off >= 1; off >>= 1)
                su += __shfl_xor_sync(0xffffffffu, su, off);
            rsum[i] = su;
        }
#pragma unroll
        for (int i = 0; i < 4; i++) {
            lrow[i] = lrow[i] * alpha[i] + rsum[i];
            mrow[i] = mnew[i];
#pragma unroll
            for (int j = 0; j < 4; j++) acc[i][j] *= alpha[i];
        }

        // Stage P transposed: Ps[n*64 + m]
#pragma unroll
        for (int j = 0; j < 4; j++) {
            float4 pv = make_float4(s[0][j], s[1][j], s[2][j], s[3][j]);
            *(float4*)&Ps[(tx * 4 + j) * 64 + ty * 4] = pv;
        }
        __syncthreads();

        // O[m][d] += sum_n P[m][n] * V[n][d]
#pragma unroll 8
        for (int n = 0; n < 64; n++) {
            const float4 pv = *(const float4*)&Ps[n * 64 + ty * 4];
            const float4 vv = *(const float4*)&Vs[n * 64 + tx * 4];
            const float pr[4] = {pv.x, pv.y, pv.z, pv.w};
            const float vr[4] = {vv.x, vv.y, vv.z, vv.w};
#pragma unroll
            for (int i = 0; i < 4; i++)
#pragma unroll
                for (int j = 0; j < 4; j++)
                    acc[i][j] += pr[i] * vr[j];
        }
    }

    // Epilogue: O /= l, write [b*T + q0+m, h*64 + d]
#pragma unroll
    for (int i = 0; i < 4; i++) {
        const float inv = 1.f / lrow[i];
        const size_t r = (size_t)(b * TT + q0 + ty * 4 + i) * DD + h * DKK + tx * 4;
        float4 o = make_float4(acc[i][0] * inv, acc[i][1] * inv,
                               acc[i][2] * inv, acc[i][3] * inv);
        *(float4*)(out + r) = o;
    }
}

// ---------------------------------------------------------------------------
// LayerNorm over last dim (1024). One block of 256 threads per row.
// ---------------------------------------------------------------------------
__global__ __launch_bounds__(256)
void ln_kernel(const float* __restrict__ X, const float* __restrict__ gamma,
               const float* __restrict__ beta, float* __restrict__ Y)
{
    __shared__ float red[8];
    const int row = blockIdx.x;
    const int tid = threadIdx.x;
    const float4 v = *(const float4*)(X + (size_t)row * DD + tid * 4);

    float s = v.x + v.y + v.z + v.w;
#pragma unroll
    for (int off = 16; off >= 1; off >>= 1)
        s += __shfl_xor_sync(0xffffffffu, s, off);
    if ((tid & 31) == 0) red[tid >> 5] = s;
    __syncthreads();
    float tot = red[0] + red[1] + red[2] + red[3] + red[4] + red[5] + red[6] + red[7];
    const float mean = tot * (1.f / 1024.f);
    __syncthreads();

    const float dx = v.x - mean, dy = v.y - mean, dz = v.z - mean, dw = v.w - mean;
    float ss = dx * dx + dy * dy + dz * dz + dw * dw;
#pragma unroll
    for (int off = 16; off >= 1; off >>= 1)
        ss += __shfl_xor_sync(0xffffffffu, ss, off);
    if ((tid & 31) == 0) red[tid >> 5] = ss;
    __syncthreads();
    float var = (red[0] + red[1] + red[2] + red[3] + red[4] + red[5] + red[6] + red[7])
                * (1.f / 1024.f);
    const float rstd = rsqrtf(var + 1e-5f);

    const int c = tid * 4;
    const float4 g = *(const float4*)(gamma + c);
    const float4 be = *(const float4*)(beta + c);
    float4 o;
    o.x = dx * rstd * g.x + be.x;
    o.y = dy * rstd * g.y + be.y;
    o.z = dz * rstd * g.z + be.z;
    o.w = dw * rstd * g.w + be.w;
    *(float4*)(Y + (size_t)row * DD + c) = o;
}

// ---------------------------------------------------------------------------
extern "C" void kernel_launch(void* const* d_in, const int* in_sizes, int n_in,
                              void* d_out, int out_size)
{
    const float* x     = (const float*)d_in[0];
    const float* Wqkv  = (const float*)d_in[1];
    const float* bqkv  = (const float*)d_in[2];
    const float* Wout  = (const float*)d_in[3];
    const float* bout  = (const float*)d_in[4];
    const float* gamma = (const float*)d_in[5];
    const float* beta  = (const float*)d_in[6];
    float* out = (float*)d_out;

    float *qkv, *att, *res;
    cudaGetSymbolAddress((void**)&qkv, g_qkv);
    cudaGetSymbolAddress((void**)&att, g_att);
    cudaGetSymbolAddress((void**)&res, g_res);

    cudaFuncSetAttribute(attn_kernel, cudaFuncAttributeMaxDynamicSharedMemorySize,
                         64 * 1024);

    // 1. QKV projection + bias
    {
        dim3 grid(D3 / 128, NTOK / 128);
        sgemm_kernel<false><<<grid, 256>>>(x, Wqkv, bqkv, nullptr, qkv,
                                           NTOK, D3, DD);
    }
    // 2. Attention
    {
        dim3 grid(TT / 64, BB * HH);
        attn_kernel<<<grid, 256, 64 * 1024>>>(qkv, att);
    }
    // 3. Output projection + bias + residual
    {
        dim3 grid(DD / 128, NTOK / 128);
        sgemm_kernel<true><<<grid, 256>>>(att, Wout, bout, x, res,
                                          NTOK, DD, DD);
    }
    // 4. LayerNorm
    ln_kernel<<<NTOK, 256>>>(res, gamma, beta, out);
}

// round 2
// speedup vs baseline: 2.0504x; 2.0504x over previous
#include <cuda_runtime.h>
#include <mma.h>
#include <math.h>

using namespace nvcuda;

#define BB 4
#define TT 2048
#define DD 1024
#define HH 16
#define DKK 64
#define NTOK (BB*TT)      // 8192
#define D3 (3*DD)         // 3072

// Scratch (allocation-free rule: __device__ globals)
__device__ float g_qkv[NTOK * D3];   // 96 MB  (raw QKV, bias NOT added)
__device__ float g_att[NTOK * DD];   // 32 MB  (attention output)
__device__ float g_res[NTOK * DD];   // 32 MB  (raw out-proj, bias/res NOT added)

__device__ __forceinline__ float to_tf32(float x) {
    float r; asm("cvt.rna.tf32.f32 %0, %1;" : "=f"(r) : "f"(x)); return r;
}

// ---------------------------------------------------------------------------
// tf32 wmma GEMM: C[M,N] = A[M,K] @ B[K,N]   (raw, no epilogue)
// Block tile 128x128, K-tile 32, 256 threads = 8 warps (4x2), warp tile 32x64.
// ---------------------------------------------------------------------------
__global__ __launch_bounds__(256)
void gemm_tf32(const float* __restrict__ A, const float* __restrict__ Bm,
               float* __restrict__ C, int M, int N, int K)
{
    __shared__ float As[128][40];   // ld 40 floats = 160B (32B multiple)
    __shared__ float Bs[32][136];   // ld 136 floats = 544B (32B multiple)

    const int tid = threadIdx.x;
    const int w  = tid >> 5;
    const int wm = w >> 1;          // 0..3
    const int wn = w & 1;           // 0..1
    const int row0 = blockIdx.y * 128;
    const int col0 = blockIdx.x * 128;

    wmma::fragment<wmma::accumulator, 16, 16, 8, float> c[2][4];
#pragma unroll
    for (int i = 0; i < 2; i++)
#pragma unroll
        for (int j = 0; j < 4; j++) wmma::fill_fragment(c[i][j], 0.f);

    const int arow  = tid >> 1;
    const int acolg = (tid & 1) * 16;
    const int brow  = tid >> 3;
    const int bcolg = (tid & 7) * 16;
    const float* Ag = A + (size_t)(row0 + arow) * K + acolg;
    const float* Bg = Bm + (size_t)brow * N + col0 + bcolg;

    for (int k0 = 0; k0 < K; k0 += 32) {
#pragma unroll
        for (int i = 0; i < 4; i++) {
            float4 av = *(const float4*)(Ag + k0 + i * 4);
            As[arow][acolg + i * 4 + 0] = to_tf32(av.x);
            As[arow][acolg + i * 4 + 1] = to_tf32(av.y);
            As[arow][acolg + i * 4 + 2] = to_tf32(av.z);
            As[arow][acolg + i * 4 + 3] = to_tf32(av.w);
            float4 bv = *(const float4*)(Bg + (size_t)k0 * N + i * 4);
            Bs[brow][bcolg + i * 4 + 0] = to_tf32(bv.x);
            Bs[brow][bcolg + i * 4 + 1] = to_tf32(bv.y);
            Bs[brow][bcolg + i * 4 + 2] = to_tf32(bv.z);
            Bs[brow][bcolg + i * 4 + 3] = to_tf32(bv.w);
        }
        __syncthreads();
#pragma unroll
        for (int ks = 0; ks < 4; ks++) {
            wmma::fragment<wmma::matrix_a, 16, 16, 8, wmma::precision::tf32, wmma::row_major> a[2];
            wmma::fragment<wmma::matrix_b, 16, 16, 8, wmma::precision::tf32, wmma::row_major> b[4];
#pragma unroll
            for (int i = 0; i < 2; i++)
                wmma::load_matrix_sync(a[i], &As[wm * 32 + i * 16][ks * 8], 40);
#pragma unroll
            for (int j = 0; j < 4; j++)
                wmma::load_matrix_sync(b[j], &Bs[ks * 8][wn * 64 + j * 16], 136);
#pragma unroll
            for (int i = 0; i < 2; i++)
#pragma unroll
                for (int j = 0; j < 4; j++)
                    wmma::mma_sync(c[i][j], a[i], b[j], c[i][j]);
        }
        __syncthreads();
    }

#pragma unroll
    for (int i = 0; i < 2; i++)
#pragma unroll
        for (int j = 0; j < 4; j++)
            wmma::store_matrix_sync(
                C + (size_t)(row0 + wm * 32 + i * 16) * N + col0 + wn * 64 + j * 16,
                c[i][j], N, wmma::mem_row_major);
}

// ---------------------------------------------------------------------------
// Flash attention, tf32 wmma for QK^T and P·V, fp32 online softmax.
// Block = 256 thr (8 warps), q-tile 64, key-tile 64, dk=64.
// QKV bias is fused into the tile loads (qkv buffer holds raw GEMM output).
// smem: Qs,Ks,Vs,Ss,Os [64][72] + row stats + bias.
// ---------------------------------------------------------------------------
#define ALD 72   // 288B rows (32B multiple)

__global__ __launch_bounds__(256)
void attn_tf32(const float* __restrict__ qkv, const float* __restrict__ bqkv,
               float* __restrict__ out)
{
    extern __shared__ float sh[];
    float* Qs = sh;                  // [64][72] tf32
    float* Ks = Qs + 64 * ALD;       // [64][72] tf32
    float* Vs = Ks + 64 * ALD;       // [64][72] tf32
    float* Ss = Vs + 64 * ALD;       // [64][72] S / P / PV staging
    float* Os = Ss + 64 * ALD;       // [64][72] fp32 O accumulator
    float* sm_m = Os + 64 * ALD;     // [64]
    float* sm_l = sm_m + 64;         // [64]
    float* sm_a = sm_l + 64;         // [64]
    float* sbias = sm_a + 64;        // [192] bq|bk|bv for this head

    const int tid = threadIdx.x;
    const int w  = tid >> 5;
    const int wm = w >> 1;           // 0..3 (16-row S/O stripe)
    const int wn = w & 1;            // 0..1 (32-col stripe)
    const int q0 = blockIdx.x * 64;
    const int bh = blockIdx.y;
    const int b  = bh >> 4;
    const int h  = bh & 15;

    const float* base = qkv + (size_t)(b * TT) * D3 + h * DKK;

    if (tid < 192) sbias[tid] = bqkv[(tid >> 6) * DD + h * DKK + (tid & 63)];
    if (tid < 64) { sm_m[tid] = -1e30f; sm_l[tid] = 0.f; }
#pragma unroll
    for (int it = 0; it < 16; it++) {
        int idx = tid + it * 256;
        Os[(idx >> 6) * ALD + (idx & 63)] = 0.f;
    }
    __syncthreads();

    // Q tile (with bias), tf32
#pragma unroll
    for (int it = 0; it < 4; it++) {
        const int idx = tid + it * 256;
        const int r = idx >> 4;
        const int cg = (idx & 15) * 4;
        float4 v = *(const float4*)(base + (size_t)(q0 + r) * D3 + cg);
        Qs[r * ALD + cg + 0] = to_tf32(v.x + sbias[cg + 0]);
        Qs[r * ALD + cg + 1] = to_tf32(v.y + sbias[cg + 1]);
        Qs[r * ALD + cg + 2] = to_tf32(v.z + sbias[cg + 2]);
        Qs[r * ALD + cg + 3] = to_tf32(v.w + sbias[cg + 3]);
    }

    const int r4 = tid >> 2;         // softmax row 0..63
    const int qq = tid & 3;          // quarter 0..3

    for (int kt = 0; kt < TT / 64; kt++) {
        __syncthreads();
        // K,V tiles (with bias), tf32
#pragma unroll
        for (int it = 0; it < 4; it++) {
            const int idx = tid + it * 256;
            const int r = idx >> 4;
            const int cg = (idx & 15) * 4;
            const size_t trow = (size_t)(kt * 64 + r) * D3;
            float4 kv = *(const float4*)(base + DD + trow + cg);
            Ks[r * ALD + cg + 0] = to_tf32(kv.x + sbias[64 + cg + 0]);
            Ks[r * ALD + cg + 1] = to_tf32(kv.y + sbias[64 + cg + 1]);
            Ks[r * ALD + cg + 2] = to_tf32(kv.z + sbias[64 + cg + 2]);
            Ks[r * ALD + cg + 3] = to_tf32(kv.w + sbias[64 + cg + 3]);
            float4 vv = *(const float4*)(base + 2 * DD + trow + cg);
            Vs[r * ALD + cg + 0] = to_tf32(vv.x + sbias[128 + cg + 0]);
            Vs[r * ALD + cg + 1] = to_tf32(vv.y + sbias[128 + cg + 1]);
            Vs[r * ALD + cg + 2] = to_tf32(vv.z + sbias[128 + cg + 2]);
            Vs[r * ALD + cg + 3] = to_tf32(vv.w + sbias[128 + cg + 3]);
        }
        __syncthreads();

        // S = Q @ K^T  (warp tile 16x32 = 1x2 frags)
        {
            wmma::fragment<wmma::accumulator, 16, 16, 8, float> sfr[2];
            wmma::fill_fragment(sfr[0], 0.f);
            wmma::fill_fragment(sfr[1], 0.f);
#pragma unroll
            for (int ks = 0; ks < 8; ks++) {
                wmma::fragment<wmma::matrix_a, 16, 16, 8, wmma::precision::tf32, wmma::row_major> a;
                wmma::fragment<wmma::matrix_b, 16, 16, 8, wmma::precision::tf32, wmma::col_major> bk;
                wmma::load_matrix_sync(a, &Qs[(wm * 16) * ALD + ks * 8], ALD);
#pragma unroll
                for (int j = 0; j < 2; j++) {
                    wmma::load_matrix_sync(bk, &Ks[(wn * 32 + j * 16) * ALD + ks * 8], ALD);
                    wmma::mma_sync(sfr[j], a, bk, sfr[j]);
                }
            }
#pragma unroll
            for (int j = 0; j < 2; j++)
                wmma::store_matrix_sync(&Ss[(wm * 16) * ALD + wn * 32 + j * 16],
                                        sfr[j], ALD, wmma::mem_row_major);
        }
        __syncthreads();

        // Online softmax: 4 threads per row, 16 cols each.
        {
            float sv[16];
            float mx = -1e30f;
#pragma unroll
            for (int cc = 0; cc < 16; cc++) {
                sv[cc] = Ss[r4 * ALD + qq * 16 + cc] * 0.125f;
                mx = fmaxf(mx, sv[cc]);
            }
            mx = fmaxf(mx, __shfl_xor_sync(0xffffffffu, mx, 1));
            mx = fmaxf(mx, __shfl_xor_sync(0xffffffffu, mx, 2));
            const float mold = sm_m[r4];
            const float mnew = fmaxf(mold, mx);
            const float alpha = __expf(mold - mnew);
            float su = 0.f;
#pragma unroll
            for (int cc = 0; cc < 16; cc++) {
                const float e = __expf(sv[cc] - mnew);
                su += e;
                Ss[r4 * ALD + qq * 16 + cc] = to_tf32(e);
            }
            su += __shfl_xor_sync(0xffffffffu, su, 1);
            su += __shfl_xor_sync(0xffffffffu, su, 2);
            if (qq == 0) {
                sm_l[r4] = sm_l[r4] * alpha + su;
                sm_m[r4] = mnew;
                sm_a[r4] = alpha;
            }
        }
        __syncthreads();

        // PV = P @ V  (warp tile 16x32)
        wmma::fragment<wmma::accumulator, 16, 16, 8, float> ofr[2];
        wmma::fill_fragment(ofr[0], 0.f);
        wmma::fill_fragment(ofr[1], 0.f);
#pragma unroll
        for (int ks = 0; ks < 8; ks++) {
            wmma::fragment<wmma::matrix_a, 16, 16, 8, wmma::precision::tf32, wmma::row_major> p;
            wmma::fragment<wmma::matrix_b, 16, 16, 8, wmma::precision::tf32, wmma::row_major> vb;
            wmma::load_matrix_sync(p, &Ss[(wm * 16) * ALD + ks * 8], ALD);
#pragma unroll
            for (int j = 0; j < 2; j++) {
                wmma::load_matrix_sync(vb, &Vs[(ks * 8) * ALD + wn * 32 + j * 16], ALD);
                wmma::mma_sync(ofr[j], p, vb, ofr[j]);
            }
        }
        __syncthreads();   // all P reads done before overwriting Ss
#pragma unroll
        for (int j = 0; j < 2; j++)
            wmma::store_matrix_sync(&Ss[(wm * 16) * ALD + wn * 32 + j * 16],
                                    ofr[j], ALD, wmma::mem_row_major);
        __syncthreads();

        // O = O * alpha(row) + PV
        {
            const float al = sm_a[r4];
#pragma unroll
            for (int cc = 0; cc < 16; cc++) {
                const int c = qq * 16 + cc;
                Os[r4 * ALD + c] = Os[r4 * ALD + c] * al + Ss[r4 * ALD + c];
            }
        }
    }
    __syncthreads();

    // Epilogue: O / l  ->  out[b*T + q0 + r][h*64 + d]
    {
        const float inv = 1.f / sm_l[r4];
        const size_t orow = (size_t)(b * TT + q0 + r4) * DD + h * DKK;
#pragma unroll
        for (int cc = 0; cc < 16; cc += 4) {
            const int c = qq * 16 + cc;
            float4 o = make_float4(Os[r4 * ALD + c + 0] * inv,
                                   Os[r4 * ALD + c + 1] * inv,
                                   Os[r4 * ALD + c + 2] * inv,
                                   Os[r4 * ALD + c + 3] * inv);
            *(float4*)(out + orow + c) = o;
        }
    }
}

// ---------------------------------------------------------------------------
// Fused: res = x + C_raw + b_out ; LayerNorm(res) * gamma + beta
// ---------------------------------------------------------------------------
__global__ __launch_bounds__(256)
void ln_fused(const float* __restrict__ Craw, const float* __restrict__ x,
              const float* __restrict__ bout, const float* __restrict__ gamma,
              const float* __restrict__ beta, float* __restrict__ Y)
{
    __shared__ float red[8];
    const int row = blockIdx.x;
    const int tid = threadIdx.x;
    const int c = tid * 4;
    const float4 cv = *(const float4*)(Craw + (size_t)row * DD + c);
    const float4 xv = *(const float4*)(x + (size_t)row * DD + c);
    const float4 bv = *(const float4*)(bout + c);
    float4 v;
    v.x = cv.x + xv.x + bv.x;
    v.y = cv.y + xv.y + bv.y;
    v.z = cv.z + xv.z + bv.z;
    v.w = cv.w + xv.w + bv.w;

    float s = v.x + v.y + v.z + v.w;
#pragma unroll
    for (int off = 16; off >= 1; off >>= 1)
        s += __shfl_xor_sync(0xffffffffu, s, off);
    if ((tid & 31) == 0) red[tid >> 5] = s;
    __syncthreads();
    float tot = red[0] + red[1] + red[2] + red[3] + red[4] + red[5] + red[6] + red[7];
    const float mean = tot * (1.f / 1024.f);
    __syncthreads();

    const float dx = v.x - mean, dy = v.y - mean, dz = v.z - mean, dw = v.w - mean;
    float ss = dx * dx + dy * dy + dz * dz + dw * dw;
#pragma unroll
    for (int off = 16; off >= 1; off >>= 1)
        ss += __shfl_xor_sync(0xffffffffu, ss, off);
    if ((tid & 31) == 0) red[tid >> 5] = ss;
    __syncthreads();
    float var = (red[0] + red[1] + red[2] + red[3] + red[4] + red[5] + red[6] + red[7])
                * (1.f / 1024.f);
    const float rstd = rsqrtf(var + 1e-5f);

    const float4 g = *(const float4*)(gamma + c);
    const float4 be = *(const float4*)(beta + c);
    float4 o;
    o.x = dx * rstd * g.x + be.x;
    o.y = dy * rstd * g.y + be.y;
    o.z = dz * rstd * g.z + be.z;
    o.w = dw * rstd * g.w + be.w;
    *(float4*)(Y + (size_t)row * DD + c) = o;
}

// ---------------------------------------------------------------------------
extern "C" void kernel_launch(void* const* d_in, const int* in_sizes, int n_in,
                              void* d_out, int out_size)
{
    const float* x     = (const float*)d_in[0];
    const float* Wqkv  = (const float*)d_in[1];
    const float* bqkv  = (const float*)d_in[2];
    const float* Wout  = (const float*)d_in[3];
    const float* bout  = (const float*)d_in[4];
    const float* gamma = (const float*)d_in[5];
    const float* beta  = (const float*)d_in[6];
    float* out = (float*)d_out;

    float *qkv, *att, *res;
    cudaGetSymbolAddress((void**)&qkv, g_qkv);
    cudaGetSymbolAddress((void**)&att, g_att);
    cudaGetSymbolAddress((void**)&res, g_res);

    static const int ATTN_SMEM = (5 * 64 * ALD + 3 * 64 + 192) * 4;
    cudaFuncSetAttribute(attn_tf32, cudaFuncAttributeMaxDynamicSharedMemorySize,
                         ATTN_SMEM);

    // 1. QKV projection (raw; bias fused into attention loads)
    {
        dim3 grid(D3 / 128, NTOK / 128);
        gemm_tf32<<<grid, 256>>>(x, Wqkv, qkv, NTOK, D3, DD);
    }
    // 2. Attention (tf32 tensor cores, bias fused)
    {
        dim3 grid(TT / 64, BB * HH);
        attn_tf32<<<grid, 256, ATTN_SMEM>>>(qkv, bqkv, att);
    }
    // 3. Output projection (raw; bias+residual fused into LN)
    {
        dim3 grid(DD / 128, NTOK / 128);
        gemm_tf32<<<grid, 256>>>(att, Wout, res, NTOK, DD, DD);
    }
    // 4. res = x + C + b_out, then LayerNorm
    ln_fused<<<NTOK, 256>>>(res, x, bout, gamma, beta, out);
}

// round 3
// speedup vs baseline: 4.4431x; 2.1669x over previous
#include <cuda_runtime.h>
#include <cuda_bf16.h>
#include <mma.h>
#include <math.h>

using namespace nvcuda;

#define BB 4
#define TT 2048
#define DD 1024
#define HH 16
#define DKK 64
#define NTOK (BB*TT)      // 8192
#define D3 (3*DD)         // 3072

// Scratch (allocation-free rule: __device__ globals)
__device__ float g_qkv[NTOK * D3];   // 96 MB  (raw QKV fp32, bias NOT added)
__device__ float g_att[NTOK * DD];   // 32 MB  (attention output fp32)
__device__ float g_res[NTOK * DD];   // 32 MB  (raw out-proj fp32)

__device__ __forceinline__ __nv_bfloat16 to_bf16(float x) {
    return __float2bfloat16_rn(x);
}

// ---------------------------------------------------------------------------
// bf16 wmma GEMM: C[M,N] = A[M,K] @ B[K,N]   (raw fp32 out, no epilogue)
// Block tile 128x128, K-tile 32, 256 threads = 8 warps (4x2), warp tile 32x64.
// A,B are fp32 in global; converted to bf16 on the smem store.
// ---------------------------------------------------------------------------
__global__ __launch_bounds__(256)
void gemm_bf16(const float* __restrict__ A, const float* __restrict__ Bm,
               float* __restrict__ C, int M, int N, int K)
{
    __shared__ __nv_bfloat16 As[128][40];   // 80B rows (16B multiple)
    __shared__ __nv_bfloat16 Bs[32][136];   // 272B rows (16B multiple)

    const int tid = threadIdx.x;
    const int w  = tid >> 5;
    const int wm = w >> 1;          // 0..3
    const int wn = w & 1;           // 0..1
    const int row0 = blockIdx.y * 128;
    const int col0 = blockIdx.x * 128;

    wmma::fragment<wmma::accumulator, 16, 16, 16, float> c[2][4];
#pragma unroll
    for (int i = 0; i < 2; i++)
#pragma unroll
        for (int j = 0; j < 4; j++) wmma::fill_fragment(c[i][j], 0.f);

    const int arow  = tid >> 1;
    const int acolg = (tid & 1) * 16;
    const int brow  = tid >> 3;
    const int bcolg = (tid & 7) * 16;
    const float* Ag = A + (size_t)(row0 + arow) * K + acolg;
    const float* Bg = Bm + (size_t)brow * N + col0 + bcolg;

    for (int k0 = 0; k0 < K; k0 += 32) {
#pragma unroll
        for (int i = 0; i < 4; i++) {
            float4 av = *(const float4*)(Ag + k0 + i * 4);
            As[arow][acolg + i * 4 + 0] = to_bf16(av.x);
            As[arow][acolg + i * 4 + 1] = to_bf16(av.y);
            As[arow][acolg + i * 4 + 2] = to_bf16(av.z);
            As[arow][acolg + i * 4 + 3] = to_bf16(av.w);
            float4 bv = *(const float4*)(Bg + (size_t)k0 * N + i * 4);
            Bs[brow][bcolg + i * 4 + 0] = to_bf16(bv.x);
            Bs[brow][bcolg + i * 4 + 1] = to_bf16(bv.y);
            Bs[brow][bcolg + i * 4 + 2] = to_bf16(bv.z);
            Bs[brow][bcolg + i * 4 + 3] = to_bf16(bv.w);
        }
        __syncthreads();
#pragma unroll
        for (int ks = 0; ks < 2; ks++) {
            wmma::fragment<wmma::matrix_a, 16, 16, 16, __nv_bfloat16, wmma::row_major> a[2];
            wmma::fragment<wmma::matrix_b, 16, 16, 16, __nv_bfloat16, wmma::row_major> b[4];
#pragma unroll
            for (int i = 0; i < 2; i++)
                wmma::load_matrix_sync(a[i], &As[wm * 32 + i * 16][ks * 16], 40);
#pragma unroll
            for (int j = 0; j < 4; j++)
                wmma::load_matrix_sync(b[j], &Bs[ks * 16][wn * 64 + j * 16], 136);
#pragma unroll
            for (int i = 0; i < 2; i++)
#pragma unroll
                for (int j = 0; j < 4; j++)
                    wmma::mma_sync(c[i][j], a[i], b[j], c[i][j]);
        }
        __syncthreads();
    }

#pragma unroll
    for (int i = 0; i < 2; i++)
#pragma unroll
        for (int j = 0; j < 4; j++)
            wmma::store_matrix_sync(
                C + (size_t)(row0 + wm * 32 + i * 16) * N + col0 + wn * 64 + j * 16,
                c[i][j], N, wmma::mem_row_major);
}

// ---------------------------------------------------------------------------
// Flash attention, bf16 wmma for QK^T and P·V, fp32 online softmax.
// Block = 256 thr (8 warps), q-tile 64, key-tile 64, dk=64.
// QKV bias fused into tile loads (qkv buffer holds raw fp32 GEMM output).
// ---------------------------------------------------------------------------
#define ALD 72   // element stride for 64-wide tiles (bf16: 144B, fp32: 288B)

__global__ __launch_bounds__(256)
void attn_bf16(const float* __restrict__ qkv, const float* __restrict__ bqkv,
               float* __restrict__ out)
{
    extern __shared__ char shraw[];
    __nv_bfloat16* Qs = (__nv_bfloat16*)shraw;                 // [64][72] bf16
    __nv_bfloat16* Ks = Qs + 64 * ALD;                          // [64][72] bf16
    __nv_bfloat16* Vs = Ks + 64 * ALD;                          // [64][72] bf16
    __nv_bfloat16* Ps = Vs + 64 * ALD;                          // [64][72] bf16
    float* Ss   = (float*)(Ps + 64 * ALD);                      // [64][72] fp32 S / PV stage
    float* Os   = Ss + 64 * ALD;                                // [64][72] fp32 O accum
    float* sm_m = Os + 64 * ALD;                                // [64]
    float* sm_l = sm_m + 64;                                    // [64]
    float* sm_a = sm_l + 64;                                    // [64]
    float* sbias = sm_a + 64;                                   // [192]

    const int tid = threadIdx.x;
    const int w  = tid >> 5;
    const int wm = w >> 1;           // 0..3 (16-row stripe)
    const int wn = w & 1;            // 0..1 (32-col stripe)
    const int q0 = blockIdx.x * 64;
    const int bh = blockIdx.y;
    const int b  = bh >> 4;
    const int h  = bh & 15;

    const float* base = qkv + (size_t)(b * TT) * D3 + h * DKK;

    if (tid < 192) sbias[tid] = bqkv[(tid >> 6) * DD + h * DKK + (tid & 63)];
    if (tid < 64) { sm_m[tid] = -1e30f; sm_l[tid] = 0.f; }
#pragma unroll
    for (int it = 0; it < 16; it++) {
        int idx = tid + it * 256;
        Os[(idx >> 6) * ALD + (idx & 63)] = 0.f;
    }
    __syncthreads();

    // Q tile (with bias) -> bf16
#pragma unroll
    for (int it = 0; it < 4; it++) {
        const int idx = tid + it * 256;
        const int r = idx >> 4;
        const int cg = (idx & 15) * 4;
        float4 v = *(const float4*)(base + (size_t)(q0 + r) * D3 + cg);
        Qs[r * ALD + cg + 0] = to_bf16(v.x + sbias[cg + 0]);
        Qs[r * ALD + cg + 1] = to_bf16(v.y + sbias[cg + 1]);
        Qs[r * ALD + cg + 2] = to_bf16(v.z + sbias[cg + 2]);
        Qs[r * ALD + cg + 3] = to_bf16(v.w + sbias[cg + 3]);
    }

    const int r4 = tid >> 2;         // softmax row 0..63
    const int qq = tid & 3;          // quarter 0..3

    for (int kt = 0; kt < TT / 64; kt++) {
        __syncthreads();
        // K,V tiles (with bias) -> bf16
#pragma unroll
        for (int it = 0; it < 4; it++) {
            const int idx = tid + it * 256;
            const int r = idx >> 4;
            const int cg = (idx & 15) * 4;
            const size_t trow = (size_t)(kt * 64 + r) * D3;
            float4 kv = *(const float4*)(base + DD + trow + cg);
            Ks[r * ALD + cg + 0] = to_bf16(kv.x + sbias[64 + cg + 0]);
            Ks[r * ALD + cg + 1] = to_bf16(kv.y + sbias[64 + cg + 1]);
            Ks[r * ALD + cg + 2] = to_bf16(kv.z + sbias[64 + cg + 2]);
            Ks[r * ALD + cg + 3] = to_bf16(kv.w + sbias[64 + cg + 3]);
            float4 vv = *(const float4*)(base + 2 * DD + trow + cg);
            Vs[r * ALD + cg + 0] = to_bf16(vv.x + sbias[128 + cg + 0]);
            Vs[r * ALD + cg + 1] = to_bf16(vv.y + sbias[128 + cg + 1]);
            Vs[r * ALD + cg + 2] = to_bf16(vv.z + sbias[128 + cg + 2]);
            Vs[r * ALD + cg + 3] = to_bf16(vv.w + sbias[128 + cg + 3]);
        }
        __syncthreads();

        // S = Q @ K^T  (warp tile 16x32)
        {
            wmma::fragment<wmma::accumulator, 16, 16, 16, float> sfr[2];
            wmma::fill_fragment(sfr[0], 0.f);
            wmma::fill_fragment(sfr[1], 0.f);
#pragma unroll
            for (int ks = 0; ks < 4; ks++) {
                wmma::fragment<wmma::matrix_a, 16, 16, 16, __nv_bfloat16, wmma::row_major> a;
                wmma::fragment<wmma::matrix_b, 16, 16, 16, __nv_bfloat16, wmma::col_major> bk;
                wmma::load_matrix_sync(a, &Qs[(wm * 16) * ALD + ks * 16], ALD);
#pragma unroll
                for (int j = 0; j < 2; j++) {
                    wmma::load_matrix_sync(bk, &Ks[(wn * 32 + j * 16) * ALD + ks * 16], ALD);
                    wmma::mma_sync(sfr[j], a, bk, sfr[j]);
                }
            }
#pragma unroll
            for (int j = 0; j < 2; j++)
                wmma::store_matrix_sync(&Ss[(wm * 16) * ALD + wn * 32 + j * 16],
                                        sfr[j], ALD, wmma::mem_row_major);
        }
        __syncthreads();

        // Online softmax: 4 threads per row, 16 cols each; P -> bf16
        {
            float sv[16];
            float mx = -1e30f;
#pragma unroll
            for (int cc = 0; cc < 16; cc++) {
                sv[cc] = Ss[r4 * ALD + qq * 16 + cc] * 0.125f;
                mx = fmaxf(mx, sv[cc]);
            }
            mx = fmaxf(mx, __shfl_xor_sync(0xffffffffu, mx, 1));
            mx = fmaxf(mx, __shfl_xor_sync(0xffffffffu, mx, 2));
            const float mold = sm_m[r4];
            const float mnew = fmaxf(mold, mx);
            const float alpha = __expf(mold - mnew);
            float su = 0.f;
#pragma unroll
            for (int cc = 0; cc < 16; cc++) {
                const float e = __expf(sv[cc] - mnew);
                su += e;
                Ps[r4 * ALD + qq * 16 + cc] = to_bf16(e);
            }
            su += __shfl_xor_sync(0xffffffffu, su, 1);
            su += __shfl_xor_sync(0xffffffffu, su, 2);
            if (qq == 0) {
                sm_l[r4] = sm_l[r4] * alpha + su;
                sm_m[r4] = mnew;
                sm_a[r4] = alpha;
            }
        }
        __syncthreads();

        // PV = P @ V  (warp tile 16x32), stage into Ss
        wmma::fragment<wmma::accumulator, 16, 16, 16, float> ofr[2];
        wmma::fill_fragment(ofr[0], 0.f);
        wmma::fill_fragment(ofr[1], 0.f);
#pragma unroll
        for (int ks = 0; ks < 4; ks++) {
            wmma::fragment<wmma::matrix_a, 16, 16, 16, __nv_bfloat16, wmma::row_major> p;
            wmma::fragment<wmma::matrix_b, 16, 16, 16, __nv_bfloat16, wmma::row_major> vb;
            wmma::load_matrix_sync(p, &Ps[(wm * 16) * ALD + ks * 16], ALD);
#pragma unroll
            for (int j = 0; j < 2; j++) {
                wmma::load_matrix_sync(vb, &Vs[(ks * 16) * ALD + wn * 32 + j * 16], ALD);
                wmma::mma_sync(ofr[j], p, vb, ofr[j]);
            }
        }
#pragma unroll
        for (int j = 0; j < 2; j++)
            wmma::store_matrix_sync(&Ss[(wm * 16) * ALD + wn * 32 + j * 16],
                                    ofr[j], ALD, wmma::mem_row_major);
        __syncthreads();

        // O = O * alpha(row) + PV
        {
            const float al = sm_a[r4];
#pragma unroll
            for (int cc = 0; cc < 16; cc++) {
                const int c = qq * 16 + cc;
                Os[r4 * ALD + c] = Os[r4 * ALD + c] * al + Ss[r4 * ALD + c];
            }
        }
    }
    __syncthreads();

    // Epilogue: O / l  ->  out[b*T + q0 + r][h*64 + d]  (fp32)
    {
        const float inv = 1.f / sm_l[r4];
        const size_t orow = (size_t)(b * TT + q0 + r4) * DD + h * DKK;
#pragma unroll
        for (int cc = 0; cc < 16; cc += 4) {
            const int c = qq * 16 + cc;
            float4 o = make_float4(Os[r4 * ALD + c + 0] * inv,
                                   Os[r4 * ALD + c + 1] * inv,
                                   Os[r4 * ALD + c + 2] * inv,
                                   Os[r4 * ALD + c + 3] * inv);
            *(float4*)(out + orow + c) = o;
        }
    }
}

// ---------------------------------------------------------------------------
// Fused: res = x + C_raw + b_out ; LayerNorm(res) * gamma + beta
// ---------------------------------------------------------------------------
__global__ __launch_bounds__(256)
void ln_fused(const float* __restrict__ Craw, const float* __restrict__ x,
              const float* __restrict__ bout, const float* __restrict__ gamma,
              const float* __restrict__ beta, float* __restrict__ Y)
{
    __shared__ float red[8];
    const int row = blockIdx.x;
    const int tid = threadIdx.x;
    const int c = tid * 4;
    const float4 cv = *(const float4*)(Craw + (size_t)row * DD + c);
    const float4 xv = *(const float4*)(x + (size_t)row * DD + c);
    const float4 bv = *(const float4*)(bout + c);
    float4 v;
    v.x = cv.x + xv.x + bv.x;
    v.y = cv.y + xv.y + bv.y;
    v.z = cv.z + xv.z + bv.z;
    v.w = cv.w + xv.w + bv.w;

    float s = v.x + v.y + v.z + v.w;
#pragma unroll
    for (int off = 16; off >= 1; off >>= 1)
        s += __shfl_xor_sync(0xffffffffu, s, off);
    if ((tid & 31) == 0) red[tid >> 5] = s;
    __syncthreads();
    float tot = red[0] + red[1] + red[2] + red[3] + red[4] + red[5] + red[6] + red[7];
    const float mean = tot * (1.f / 1024.f);
    __syncthreads();

    const float dx = v.x - mean, dy = v.y - mean, dz = v.z - mean, dw = v.w - mean;
    float ss = dx * dx + dy * dy + dz * dz + dw * dw;
#pragma unroll
    for (int off = 16; off >= 1; off >>= 1)
        ss += __shfl_xor_sync(0xffffffffu, ss, off);
    if ((tid & 31) == 0) red[tid >> 5] = ss;
    __syncthreads();
    float var = (red[0] + red[1] + red[2] + red[3] + red[4] + red[5] + red[6] + red[7])
                * (1.f / 1024.f);
    const float rstd = rsqrtf(var + 1e-5f);

    const float4 g = *(const float4*)(gamma + c);
    const float4 be = *(const float4*)(beta + c);
    float4 o;
    o.x = dx * rstd * g.x + be.x;
    o.y = dy * rstd * g.y + be.y;
    o.z = dz * rstd * g.z + be.z;
    o.w = dw * rstd * g.w + be.w;
    *(float4*)(Y + (size_t)row * DD + c) = o;
}

// ---------------------------------------------------------------------------
extern "C" void kernel_launch(void* const* d_in, const int* in_sizes, int n_in,
                              void* d_out, int out_size)
{
    const float* x     = (const float*)d_in[0];
    const float* Wqkv  = (const float*)d_in[1];
    const float* bqkv  = (const float*)d_in[2];
    const float* Wout  = (const float*)d_in[3];
    const float* bout  = (const float*)d_in[4];
    const float* gamma = (const float*)d_in[5];
    const float* beta  = (const float*)d_in[6];
    float* out = (float*)d_out;

    float *qkv, *att, *res;
    cudaGetSymbolAddress((void**)&qkv, g_qkv);
    cudaGetSymbolAddress((void**)&att, g_att);
    cudaGetSymbolAddress((void**)&res, g_res);

    static const int ATTN_SMEM = (4 * 64 * ALD) * 2 + (2 * 64 * ALD) * 4
                                 + 3 * 64 * 4 + 192 * 4;
    cudaFuncSetAttribute(attn_bf16, cudaFuncAttributeMaxDynamicSharedMemorySize,
                         ATTN_SMEM);

    // 1. QKV projection (raw fp32; bias fused into attention loads)
    {
        dim3 grid(D3 / 128, NTOK / 128);
        gemm_bf16<<<grid, 256>>>(x, Wqkv, qkv, NTOK, D3, DD);
    }
    // 2. Attention (bf16 tensor cores, bias fused)
    {
        dim3 grid(TT / 64, BB * HH);
        attn_bf16<<<grid, 256, ATTN_SMEM>>>(qkv, bqkv, att);
    }
    // 3. Output projection (raw fp32; bias+residual fused into LN)
    {
        dim3 grid(DD / 128, NTOK / 128);
        gemm_bf16<<<grid, 256>>>(att, Wout, res, NTOK, DD, DD);
    }
    // 4. res = x + C + b_out, then LayerNorm
    ln_fused<<<NTOK, 256>>>(res, x, bout, gamma, beta, out);
}

// round 7
// speedup vs baseline: 5.4106x; 1.2177x over previous
#include <cuda_runtime.h>
#include <cuda_bf16.h>
#include <mma.h>
#include <math.h>
#include <cstdint>

using namespace nvcuda;

#define BB 4
#define TT 2048
#define DD 1024
#define HH 16
#define DKK 64
#define NTOK (BB*TT)      // 8192
#define D3 (3*DD)         // 3072

// Scratch (allocation-free rule: __device__ globals)
__device__ __nv_bfloat16 g_xb[NTOK * DD];      // x bf16
__device__ __nv_bfloat16 g_wqkv[DD * D3];      // W_qkv bf16 [1024,3072] row-major
__device__ __nv_bfloat16 g_wout[DD * DD];      // W_out bf16 [1024,1024] row-major
__device__ __nv_bfloat16 g_qkv[NTOK * D3];     // raw QKV bf16 (bias NOT added)
__device__ __nv_bfloat16 g_att[NTOK * DD];     // attention out bf16
__device__ float         g_res[NTOK * DD];     // raw out-proj fp32

__device__ __forceinline__ __nv_bfloat16 to_bf16(float x) { return __float2bfloat16_rn(x); }

__device__ __forceinline__ uint32_t smem_u32(const void* p) {
    uint32_t a;
    asm("{ .reg .u64 t; cvta.to.shared.u64 t, %1; cvt.u32.u64 %0, t; }" : "=r"(a) : "l"(p));
    return a;
}
__device__ __forceinline__ void cp_async16(uint32_t s, const void* g) {
    asm volatile("cp.async.cg.shared.global [%0], [%1], 16;" :: "r"(s), "l"(g) : "memory");
}
#define CP_COMMIT() asm volatile("cp.async.commit_group;" ::: "memory")
#define CP_WAIT(N)  asm volatile("cp.async.wait_group %0;" :: "n"(N) : "memory")

// ---------------------------------------------------------------------------
// cp.async double-buffered bf16 wmma GEMM: C[M,N] = A[M,K] @ B[K,N]
// Block tile 128x128, K chunk 64, 256 threads = 8 warps (4x2), warp 32x64.
// ---------------------------------------------------------------------------
#define ALD_A 72    // bf16 elements per A smem row (144B)
#define ALD_B 136   // bf16 elements per B smem row (272B)
#define OFF_A0 0
#define OFF_A1 (128*ALD_A*2)                 // 18432
#define OFF_B0 (OFF_A1 + 128*ALD_A*2)        // 36864
#define OFF_B1 (OFF_B0 + 64*ALD_B*2)         // 54272
#define GEMM_SMEM (OFF_B1 + 64*ALD_B*2)      // 71680
#define CLD 132     // fp32 staging stride

template<bool BF16_OUT>
__global__ __launch_bounds__(256)
void gemm_wb(const __nv_bfloat16* __restrict__ A, const __nv_bfloat16* __restrict__ B,
             void* __restrict__ Cout, int M, int N, int K)
{
    extern __shared__ char sh[];
    const uint32_t sb = smem_u32(sh);
    const int tid = threadIdx.x;
    const int w  = tid >> 5;
    const int wm = w >> 1;          // 0..3
    const int wn = w & 1;           // 0..1
    const int row0 = blockIdx.y * 128;
    const int col0 = blockIdx.x * 128;

    wmma::fragment<wmma::accumulator, 16, 16, 16, float> acc[2][4];
#pragma unroll
    for (int i = 0; i < 2; i++)
#pragma unroll
        for (int j = 0; j < 4; j++) wmma::fill_fragment(acc[i][j], 0.f);

    const int nchunk = K / 64;

    // issue loads for chunk c into buffer s
    auto issue = [&](int c, int s) {
        const uint32_t aB = sb + (s ? OFF_A1 : OFF_A0);
        const uint32_t bB = sb + (s ? OFF_B1 : OFF_B0);
        const __nv_bfloat16* Ag = A + (size_t)row0 * K + c * 64;
        const __nv_bfloat16* Bg = B + (size_t)(c * 64) * N + col0;
#pragma unroll
        for (int i = 0; i < 4; i++) {
            const int u = tid + i * 256;        // A: 1024 16B-chunks
            const int r = u >> 3, cc = u & 7;
            cp_async16(aB + r * (ALD_A * 2) + cc * 16, Ag + (size_t)r * K + cc * 8);
        }
#pragma unroll
        for (int i = 0; i < 4; i++) {
            const int u = tid + i * 256;        // B: 1024 16B-chunks
            const int r = u >> 4, cc = u & 15;
            cp_async16(bB + r * (ALD_B * 2) + cc * 16, Bg + (size_t)r * N + cc * 8);
        }
        CP_COMMIT();
    };

    issue(0, 0);
    for (int c = 0; c < nchunk; c++) {
        const int s = c & 1;
        if (c + 1 < nchunk) { issue(c + 1, (c + 1) & 1); CP_WAIT(1); }
        else                { CP_WAIT(0); }
        __syncthreads();

        const __nv_bfloat16* Asb = (const __nv_bfloat16*)(sh + (s ? OFF_A1 : OFF_A0));
        const __nv_bfloat16* Bsb = (const __nv_bfloat16*)(sh + (s ? OFF_B1 : OFF_B0));
#pragma unroll
        for (int ks = 0; ks < 4; ks++) {
            wmma::fragment<wmma::matrix_a, 16, 16, 16, __nv_bfloat16, wmma::row_major> a[2];
            wmma::fragment<wmma::matrix_b, 16, 16, 16, __nv_bfloat16, wmma::row_major> b[4];
#pragma unroll
            for (int i = 0; i < 2; i++)
                wmma::load_matrix_sync(a[i], Asb + (wm * 32 + i * 16) * ALD_A + ks * 16, ALD_A);
#pragma unroll
            for (int j = 0; j < 4; j++)
                wmma::load_matrix_sync(b[j], Bsb + (ks * 16) * ALD_B + wn * 64 + j * 16, ALD_B);
#pragma unroll
            for (int i = 0; i < 2; i++)
#pragma unroll
                for (int j = 0; j < 4; j++)
                    wmma::mma_sync(acc[i][j], a[i], b[j], acc[i][j]);
        }
        __syncthreads();   // compute done before next-next chunk overwrites buffer
    }

    if (BF16_OUT) {
        // stage fp32 in smem (reuses pipeline buffers), convert to bf16 global
        float* Cs = (float*)sh;
#pragma unroll
        for (int i = 0; i < 2; i++)
#pragma unroll
            for (int j = 0; j < 4; j++)
                wmma::store_matrix_sync(Cs + (wm * 32 + i * 16) * CLD + wn * 64 + j * 16,
                                        acc[i][j], CLD, wmma::mem_row_major);
        __syncthreads();
        __nv_bfloat16* C = (__nv_bfloat16*)Cout;
#pragma unroll
        for (int i = 0; i < 8; i++) {
            const int u = tid + i * 256;       // 2048 groups of 8 elems
            const int r = u >> 4, cg = (u & 15) * 8;
            const float4 v0 = *(const float4*)(Cs + r * CLD + cg);
            const float4 v1 = *(const float4*)(Cs + r * CLD + cg + 4);
            __nv_bfloat162 p0 = __floats2bfloat162_rn(v0.x, v0.y);
            __nv_bfloat162 p1 = __floats2bfloat162_rn(v0.z, v0.w);
            __nv_bfloat162 p2 = __floats2bfloat162_rn(v1.x, v1.y);
            __nv_bfloat162 p3 = __floats2bfloat162_rn(v1.z, v1.w);
            uint4 o;
            o.x = *(uint32_t*)&p0; o.y = *(uint32_t*)&p1;
            o.z = *(uint32_t*)&p2; o.w = *(uint32_t*)&p3;
            *(uint4*)(C + (size_t)(row0 + r) * N + col0 + cg) = o;
        }
    } else {
        float* C = (float*)Cout;
#pragma unroll
        for (int i = 0; i < 2; i++)
#pragma unroll
            for (int j = 0; j < 4; j++)
                wmma::store_matrix_sync(
                    C + (size_t)(row0 + wm * 32 + i * 16) * N + col0 + wn * 64 + j * 16,
                    acc[i][j], N, wmma::mem_row_major);
    }
}

// ---------------------------------------------------------------------------
// Prep: fp32 -> bf16 convert (vectorized)
// ---------------------------------------------------------------------------
__global__ __launch_bounds__(256)
void cvt_bf16_kernel(const float* __restrict__ X, __nv_bfloat16* __restrict__ Y)
{
    const int i = (blockIdx.x * 256 + threadIdx.x) * 4;
    const float4 v = *(const float4*)(X + i);
    __nv_bfloat162 a = __floats2bfloat162_rn(v.x, v.y);
    __nv_bfloat162 b = __floats2bfloat162_rn(v.z, v.w);
    uint2 o; o.x = *(uint32_t*)&a; o.y = *(uint32_t*)&b;
    *(uint2*)(Y + i) = o;
}

// ---------------------------------------------------------------------------
// Flash attention, bf16 wmma, fp32 online softmax. bf16 in (raw qkv), bf16 out.
// ---------------------------------------------------------------------------
#define ALD 72

__global__ __launch_bounds__(256)
void attn_bf16(const __nv_bfloat16* __restrict__ qkv, const float* __restrict__ bqkv,
               __nv_bfloat16* __restrict__ out)
{
    extern __shared__ char shraw[];
    __nv_bfloat16* Qs = (__nv_bfloat16*)shraw;
    __nv_bfloat16* Ks = Qs + 64 * ALD;
    __nv_bfloat16* Vs = Ks + 64 * ALD;
    __nv_bfloat16* Ps = Vs + 64 * ALD;
    float* Ss   = (float*)(Ps + 64 * ALD);
    float* Os   = Ss + 64 * ALD;
    float* sm_m = Os + 64 * ALD;
    float* sm_l = sm_m + 64;
    float* sm_a = sm_l + 64;
    float* sbias = sm_a + 64;  // [192]

    const int tid = threadIdx.x;
    const int w  = tid >> 5;
    const int wm = w >> 1;
    const int wn = w & 1;
    const int q0 = blockIdx.x * 64;
    const int bh = blockIdx.y;
    const int b  = bh >> 4;
    const int h  = bh & 15;

    const __nv_bfloat16* base = qkv + (size_t)(b * TT) * D3 + h * DKK;

    if (tid < 192) sbias[tid] = bqkv[(tid >> 6) * DD + h * DKK + (tid & 63)];
    if (tid < 64) { sm_m[tid] = -1e30f; sm_l[tid] = 0.f; }
#pragma unroll
    for (int it = 0; it < 16; it++) {
        int idx = tid + it * 256;
        Os[(idx >> 6) * ALD + (idx & 63)] = 0.f;
    }
    __syncthreads();

    // Q tile (with bias)
#pragma unroll
    for (int it = 0; it < 2; it++) {
        const int u = tid + it * 256;      // 0..511 units of 8 bf16
        const int r = u >> 3;
        const int cg = (u & 7) * 8;
        const uint4 raw = *(const uint4*)(base + (size_t)(q0 + r) * D3 + cg);
        const __nv_bfloat16* e = (const __nv_bfloat16*)&raw;
#pragma unroll
        for (int j = 0; j < 8; j++)
            Qs[r * ALD + cg + j] = to_bf16(__bfloat162float(e[j]) + sbias[cg + j]);
    }

    const int r4 = tid >> 2;
    const int qq = tid & 3;

    for (int kt = 0; kt < TT / 64; kt++) {
        __syncthreads();
#pragma unroll
        for (int it = 0; it < 2; it++) {
            const int u = tid + it * 256;
            const int r = u >> 3;
            const int cg = (u & 7) * 8;
            const size_t trow = (size_t)(kt * 64 + r) * D3;
            const uint4 kraw = *(const uint4*)(base + DD + trow + cg);
            const __nv_bfloat16* ke = (const __nv_bfloat16*)&kraw;
            const uint4 vraw = *(const uint4*)(base + 2 * DD + trow + cg);
            const __nv_bfloat16* ve = (const __nv_bfloat16*)&vraw;
#pragma unroll
            for (int j = 0; j < 8; j++) {
                Ks[r * ALD + cg + j] = to_bf16(__bfloat162float(ke[j]) + sbias[64 + cg + j]);
                Vs[r * ALD + cg + j] = to_bf16(__bfloat162float(ve[j]) + sbias[128 + cg + j]);
            }
        }
        __syncthreads();

        // S = Q @ K^T
        {
            wmma::fragment<wmma::accumulator, 16, 16, 16, float> sfr[2];
            wmma::fill_fragment(sfr[0], 0.f);
            wmma::fill_fragment(sfr[1], 0.f);
#pragma unroll
            for (int ks = 0; ks < 4; ks++) {
                wmma::fragment<wmma::matrix_a, 16, 16, 16, __nv_bfloat16, wmma::row_major> a;
                wmma::fragment<wmma::matrix_b, 16, 16, 16, __nv_bfloat16, wmma::col_major> bk;
                wmma::load_matrix_sync(a, &Qs[(wm * 16) * ALD + ks * 16], ALD);
#pragma unroll
                for (int j = 0; j < 2; j++) {
                    wmma::load_matrix_sync(bk, &Ks[(wn * 32 + j * 16) * ALD + ks * 16], ALD);
                    wmma::mma_sync(sfr[j], a, bk, sfr[j]);
                }
            }
#pragma unroll
            for (int j = 0; j < 2; j++)
                wmma::store_matrix_sync(&Ss[(wm * 16) * ALD + wn * 32 + j * 16],
                                        sfr[j], ALD, wmma::mem_row_major);
        }
        __syncthreads();

        // Online softmax (4 threads per row, 16 cols each); P -> bf16
        {
            float sv[16];
            float mx = -1e30f;
#pragma unroll
            for (int cc = 0; cc < 16; cc++) {
                sv[cc] = Ss[r4 * ALD + qq * 16 + cc] * 0.125f;
                mx = fmaxf(mx, sv[cc]);
            }
            mx = fmaxf(mx, __shfl_xor_sync(0xffffffffu, mx, 1));
            mx = fmaxf(mx, __shfl_xor_sync(0xffffffffu, mx, 2));
            const float mold = sm_m[r4];
            const float mnew = fmaxf(mold, mx);
            const float alpha = __expf(mold - mnew);
            float su = 0.f;
#pragma unroll
            for (int cc = 0; cc < 16; cc++) {
                const float e = __expf(sv[cc] - mnew);
                su += e;
                Ps[r4 * ALD + qq * 16 + cc] = to_bf16(e);
            }
            su += __shfl_xor_sync(0xffffffffu, su, 1);
            su += __shfl_xor_sync(0xffffffffu, su, 2);
            if (qq == 0) {
                sm_l[r4] = sm_l[r4] * alpha + su;
                sm_m[r4] = mnew;
                sm_a[r4] = alpha;
            }
        }
        __syncthreads();

        // PV = P @ V
        wmma::fragment<wmma::accumulator, 16, 16, 16, float> ofr[2];
        wmma::fill_fragment(ofr[0], 0.f);
        wmma::fill_fragment(ofr[1], 0.f);
#pragma unroll
        for (int ks = 0; ks < 4; ks++) {
            wmma::fragment<wmma::matrix_a, 16, 16, 16, __nv_bfloat16, wmma::row_major> p;
            wmma::fragment<wmma::matrix_b, 16, 16, 16, __nv_bfloat16, wmma::row_major> vb;
            wmma::load_matrix_sync(p, &Ps[(wm * 16) * ALD + ks * 16], ALD);
#pragma unroll
            for (int j = 0; j < 2; j++) {
                wmma::load_matrix_sync(vb, &Vs[(ks * 16) * ALD + wn * 32 + j * 16], ALD);
                wmma::mma_sync(ofr[j], p, vb, ofr[j]);
            }
        }
#pragma unroll
        for (int j = 0; j < 2; j++)
            wmma::store_matrix_sync(&Ss[(wm * 16) * ALD + wn * 32 + j * 16],
                                    ofr[j], ALD, wmma::mem_row_major);
        __syncthreads();

        {
            const float al = sm_a[r4];
#pragma unroll
            for (int cc = 0; cc < 16; cc++) {
                const int c = qq * 16 + cc;
                Os[r4 * ALD + c] = Os[r4 * ALD + c] * al + Ss[r4 * ALD + c];
            }
        }
    }
    __syncthreads();

    // Epilogue -> bf16
    {
        const float inv = 1.f / sm_l[r4];
        const size_t orow = (size_t)(b * TT + q0 + r4) * DD + h * DKK;
#pragma unroll
        for (int cc = 0; cc < 16; cc += 4) {
            const int c = qq * 16 + cc;
            __nv_bfloat162 p0 = __floats2bfloat162_rn(Os[r4 * ALD + c + 0] * inv,
                                                      Os[r4 * ALD + c + 1] * inv);
            __nv_bfloat162 p1 = __floats2bfloat162_rn(Os[r4 * ALD + c + 2] * inv,
                                                      Os[r4 * ALD + c + 3] * inv);
            uint2 o; o.x = *(uint32_t*)&p0; o.y = *(uint32_t*)&p1;
            *(uint2*)(out + orow + c) = o;
        }
    }
}

// ---------------------------------------------------------------------------
// Fused: res = x + C_raw + b_out ; LayerNorm
// ---------------------------------------------------------------------------
__global__ __launch_bounds__(256)
void ln_fused(const float* __restrict__ Craw, const float* __restrict__ x,
              const float* __restrict__ bout, const float* __restrict__ gamma,
              const float* __restrict__ beta, float* __restrict__ Y)
{
    __shared__ float red[8];
    const int row = blockIdx.x;
    const int tid = threadIdx.x;
    const int c = tid * 4;
    const float4 cv = *(const float4*)(Craw + (size_t)row * DD + c);
    const float4 xv = *(const float4*)(x + (size_t)row * DD + c);
    const float4 bv = *(const float4*)(bout + c);
    float4 v;
    v.x = cv.x + xv.x + bv.x;
    v.y = cv.y + xv.y + bv.y;
    v.z = cv.z + xv.z + bv.z;
    v.w = cv.w + xv.w + bv.w;

    float s = v.x + v.y + v.z + v.w;
#pragma unroll
    for (int off = 16; off >= 1; off >>= 1)
        s += __shfl_xor_sync(0xffffffffu, s, off);
    if ((tid & 31) == 0) red[tid >> 5] = s;
    __syncthreads();
    float tot = red[0] + red[1] + red[2] + red[3] + red[4] + red[5] + red[6] + red[7];
    const float mean = tot * (1.f / 1024.f);
    __syncthreads();

    const float dx = v.x - mean, dy = v.y - mean, dz = v.z - mean, dw = v.w - mean;
    float ss = dx * dx + dy * dy + dz * dz + dw * dw;
#pragma unroll
    for (int off = 16; off >= 1; off >>= 1)
        ss += __shfl_xor_sync(0xffffffffu, ss, off);
    if ((tid & 31) == 0) red[tid >> 5] = ss;
    __syncthreads();
    float var = (red[0] + red[1] + red[2] + red[3] + red[4] + red[5] + red[6] + red[7])
                * (1.f / 1024.f);
    const float rstd = rsqrtf(var + 1e-5f);

    const float4 g = *(const float4*)(gamma + c);
    const float4 be = *(const float4*)(beta + c);
    float4 o;
    o.x = dx * rstd * g.x + be.x;
    o.y = dy * rstd * g.y + be.y;
    o.z = dz * rstd * g.z + be.z;
    o.w = dw * rstd * g.w + be.w;
    *(float4*)(Y + (size_t)row * DD + c) = o;
}

// ---------------------------------------------------------------------------
extern "C" void kernel_launch(void* const* d_in, const int* in_sizes, int n_in,
                              void* d_out, int out_size)
{
    const float* x     = (const float*)d_in[0];
    const float* Wqkv  = (const float*)d_in[1];
    const float* bqkv  = (const float*)d_in[2];
    const float* Wout  = (const float*)d_in[3];
    const float* bout  = (const float*)d_in[4];
    const float* gamma = (const float*)d_in[5];
    const float* beta  = (const float*)d_in[6];
    float* out = (float*)d_out;

    __nv_bfloat16 *xb, *wqkv, *wout, *qkv, *att;
    float* res;
    cudaGetSymbolAddress((void**)&xb, g_xb);
    cudaGetSymbolAddress((void**)&wqkv, g_wqkv);
    cudaGetSymbolAddress((void**)&wout, g_wout);
    cudaGetSymbolAddress((void**)&qkv, g_qkv);
    cudaGetSymbolAddress((void**)&att, g_att);
    cudaGetSymbolAddress((void**)&res, g_res);

    static const int ATTN_SMEM = (4 * 64 * ALD) * 2 + (2 * 64 * ALD) * 4
                                 + 3 * 64 * 4 + 192 * 4;
    cudaFuncSetAttribute(attn_bf16, cudaFuncAttributeMaxDynamicSharedMemorySize, ATTN_SMEM);
    cudaFuncSetAttribute(gemm_wb<true>, cudaFuncAttributeMaxDynamicSharedMemorySize, GEMM_SMEM);
    cudaFuncSetAttribute(gemm_wb<false>, cudaFuncAttributeMaxDynamicSharedMemorySize, GEMM_SMEM);

    // 0. Prep: convert x, W_qkv, W_out to bf16 (row-major, no transpose)
    cvt_bf16_kernel<<<NTOK * DD / 1024, 256>>>(x, xb);
    cvt_bf16_kernel<<<DD * D3 / 1024, 256>>>(Wqkv, wqkv);
    cvt_bf16_kernel<<<DD * DD / 1024, 256>>>(Wout, wout);

    // 1. QKV projection (cp.async pipelined bf16 wmma, bf16 out; bias fused later)
    {
        dim3 grid(D3 / 128, NTOK / 128);
        gemm_wb<true><<<grid, 256, GEMM_SMEM>>>(xb, wqkv, qkv, NTOK, D3, DD);
    }
    // 2. Attention (bf16 wmma, bias fused, bf16 out)
    {
        dim3 grid(TT / 64, BB * HH);
        attn_bf16<<<grid, 256, ATTN_SMEM>>>(qkv, bqkv, att);
    }
    // 3. Output projection (fp32 out; bias+residual fused into LN)
    {
        dim3 grid(DD / 128, NTOK / 128);
        gemm_wb<false><<<grid, 256, GEMM_SMEM>>>(att, wout, res, NTOK, DD, DD);
    }
    // 4. res = x + C + b_out, then LayerNorm
    ln_fused<<<NTOK, 256>>>(res, x, bout, gamma, beta, out);
}

// round 8
// speedup vs baseline: 11.3803x; 2.1033x over previous
#include <cuda_runtime.h>
#include <cuda_bf16.h>
#include <mma.h>
#include <math.h>
#include <cstdint>

using namespace nvcuda;

#define BB 4
#define TT 2048
#define DD 1024
#define HH 16
#define DKK 64
#define NTOK (BB*TT)      // 8192
#define D3 (3*DD)         // 3072

// Scratch (allocation-free rule: __device__ globals)
__device__ __nv_bfloat16 g_xb[NTOK * DD];      // x bf16
__device__ __nv_bfloat16 g_wqkv[DD * D3];      // W_qkv bf16 row-major
__device__ __nv_bfloat16 g_wout[DD * DD];      // W_out bf16 row-major
__device__ __nv_bfloat16 g_qkv[NTOK * D3];     // QKV bf16 WITH bias
__device__ __nv_bfloat16 g_att[NTOK * DD];     // attention out bf16
__device__ float         g_res[NTOK * DD];     // raw out-proj fp32

__device__ __forceinline__ uint32_t smem_u32(const void* p) {
    uint32_t a;
    asm("{ .reg .u64 t; cvta.to.shared.u64 t, %1; cvt.u32.u64 %0, t; }" : "=r"(a) : "l"(p));
    return a;
}
__device__ __forceinline__ void cp_async16(uint32_t s, const void* g) {
    asm volatile("cp.async.cg.shared.global [%0], [%1], 16;" :: "r"(s), "l"(g) : "memory");
}
#define CP_COMMIT() asm volatile("cp.async.commit_group;" ::: "memory")
#define CP_WAIT(N)  asm volatile("cp.async.wait_group %0;" :: "n"(N) : "memory")

__device__ __forceinline__ uint32_t bf2pack(float x, float y) {
    __nv_bfloat162 p = __floats2bfloat162_rn(x, y);
    return *(uint32_t*)&p;
}
__device__ __forceinline__ void ldmx4(uint32_t& r0, uint32_t& r1, uint32_t& r2,
                                      uint32_t& r3, uint32_t addr) {
    asm volatile("ldmatrix.sync.aligned.m8n8.x4.shared.b16 {%0,%1,%2,%3}, [%4];"
                 : "=r"(r0), "=r"(r1), "=r"(r2), "=r"(r3) : "r"(addr));
}
__device__ __forceinline__ void ldmx4t(uint32_t& r0, uint32_t& r1, uint32_t& r2,
                                       uint32_t& r3, uint32_t addr) {
    asm volatile("ldmatrix.sync.aligned.m8n8.x4.trans.shared.b16 {%0,%1,%2,%3}, [%4];"
                 : "=r"(r0), "=r"(r1), "=r"(r2), "=r"(r3) : "r"(addr));
}
__device__ __forceinline__ void mma16816(float* c, const uint32_t* a,
                                         uint32_t b0, uint32_t b1) {
    asm volatile("mma.sync.aligned.m16n8k16.row.col.f32.bf16.bf16.f32 "
                 "{%0,%1,%2,%3}, {%4,%5,%6,%7}, {%8,%9}, {%0,%1,%2,%3};"
                 : "+f"(c[0]), "+f"(c[1]), "+f"(c[2]), "+f"(c[3])
                 : "r"(a[0]), "r"(a[1]), "r"(a[2]), "r"(a[3]), "r"(b0), "r"(b1));
}

// ---------------------------------------------------------------------------
// cp.async double-buffered bf16 wmma GEMM: C[M,N] = A[M,K] @ B[K,N] (+bias)
// ---------------------------------------------------------------------------
#define ALD_A 72
#define ALD_B 136
#define OFF_A0 0
#define OFF_A1 (128*ALD_A*2)
#define OFF_B0 (OFF_A1 + 128*ALD_A*2)
#define OFF_B1 (OFF_B0 + 64*ALD_B*2)
#define GEMM_SMEM (OFF_B1 + 64*ALD_B*2)
#define CLD 132

template<bool BF16_OUT>
__global__ __launch_bounds__(256, 2)
void gemm_wb(const __nv_bfloat16* __restrict__ A, const __nv_bfloat16* __restrict__ B,
             const float* __restrict__ bias, void* __restrict__ Cout,
             int M, int N, int K)
{
    extern __shared__ char sh[];
    const uint32_t sb = smem_u32(sh);
    const int tid = threadIdx.x;
    const int w  = tid >> 5;
    const int wm = w >> 1;
    const int wn = w & 1;
    const int row0 = blockIdx.y * 128;
    const int col0 = blockIdx.x * 128;

    wmma::fragment<wmma::accumulator, 16, 16, 16, float> acc[2][4];
#pragma unroll
    for (int i = 0; i < 2; i++)
#pragma unroll
        for (int j = 0; j < 4; j++) wmma::fill_fragment(acc[i][j], 0.f);

    const int nchunk = K / 64;

    auto issue = [&](int c, int s) {
        const uint32_t aB = sb + (s ? OFF_A1 : OFF_A0);
        const uint32_t bB = sb + (s ? OFF_B1 : OFF_B0);
        const __nv_bfloat16* Ag = A + (size_t)row0 * K + c * 64;
        const __nv_bfloat16* Bg = B + (size_t)(c * 64) * N + col0;
#pragma unroll
        for (int i = 0; i < 4; i++) {
            const int u = tid + i * 256;
            const int r = u >> 3, cc = u & 7;
            cp_async16(aB + r * (ALD_A * 2) + cc * 16, Ag + (size_t)r * K + cc * 8);
        }
#pragma unroll
        for (int i = 0; i < 4; i++) {
            const int u = tid + i * 256;
            const int r = u >> 4, cc = u & 15;
            cp_async16(bB + r * (ALD_B * 2) + cc * 16, Bg + (size_t)r * N + cc * 8);
        }
        CP_COMMIT();
    };

    issue(0, 0);
    for (int c = 0; c < nchunk; c++) {
        const int s = c & 1;
        if (c + 1 < nchunk) { issue(c + 1, (c + 1) & 1); CP_WAIT(1); }
        else                { CP_WAIT(0); }
        __syncthreads();

        const __nv_bfloat16* Asb = (const __nv_bfloat16*)(sh + (s ? OFF_A1 : OFF_A0));
        const __nv_bfloat16* Bsb = (const __nv_bfloat16*)(sh + (s ? OFF_B1 : OFF_B0));
#pragma unroll
        for (int ks = 0; ks < 4; ks++) {
            wmma::fragment<wmma::matrix_a, 16, 16, 16, __nv_bfloat16, wmma::row_major> a[2];
            wmma::fragment<wmma::matrix_b, 16, 16, 16, __nv_bfloat16, wmma::row_major> b[4];
#pragma unroll
            for (int i = 0; i < 2; i++)
                wmma::load_matrix_sync(a[i], Asb + (wm * 32 + i * 16) * ALD_A + ks * 16, ALD_A);
#pragma unroll
            for (int j = 0; j < 4; j++)
                wmma::load_matrix_sync(b[j], Bsb + (ks * 16) * ALD_B + wn * 64 + j * 16, ALD_B);
#pragma unroll
            for (int i = 0; i < 2; i++)
#pragma unroll
                for (int j = 0; j < 4; j++)
                    wmma::mma_sync(acc[i][j], a[i], b[j], acc[i][j]);
        }
        __syncthreads();
    }

    if (BF16_OUT) {
        float* Cs = (float*)sh;
#pragma unroll
        for (int i = 0; i < 2; i++)
#pragma unroll
            for (int j = 0; j < 4; j++)
                wmma::store_matrix_sync(Cs + (wm * 32 + i * 16) * CLD + wn * 64 + j * 16,
                                        acc[i][j], CLD, wmma::mem_row_major);
        __syncthreads();
        __nv_bfloat16* C = (__nv_bfloat16*)Cout;
#pragma unroll
        for (int i = 0; i < 8; i++) {
            const int u = tid + i * 256;
            const int r = u >> 4, cg = (u & 15) * 8;
            const float4 bv0 = *(const float4*)(bias + col0 + cg);
            const float4 bv1 = *(const float4*)(bias + col0 + cg + 4);
            const float4 v0 = *(const float4*)(Cs + r * CLD + cg);
            const float4 v1 = *(const float4*)(Cs + r * CLD + cg + 4);
            __nv_bfloat162 p0 = __floats2bfloat162_rn(v0.x + bv0.x, v0.y + bv0.y);
            __nv_bfloat162 p1 = __floats2bfloat162_rn(v0.z + bv0.z, v0.w + bv0.w);
            __nv_bfloat162 p2 = __floats2bfloat162_rn(v1.x + bv1.x, v1.y + bv1.y);
            __nv_bfloat162 p3 = __floats2bfloat162_rn(v1.z + bv1.z, v1.w + bv1.w);
            uint4 o;
            o.x = *(uint32_t*)&p0; o.y = *(uint32_t*)&p1;
            o.z = *(uint32_t*)&p2; o.w = *(uint32_t*)&p3;
            *(uint4*)(C + (size_t)(row0 + r) * N + col0 + cg) = o;
        }
    } else {
        float* C = (float*)Cout;
#pragma unroll
        for (int i = 0; i < 2; i++)
#pragma unroll
            for (int j = 0; j < 4; j++)
                wmma::store_matrix_sync(
                    C + (size_t)(row0 + wm * 32 + i * 16) * N + col0 + wn * 64 + j * 16,
                    acc[i][j], N, wmma::mem_row_major);
    }
}

// ---------------------------------------------------------------------------
// Prep: fp32 -> bf16 convert
// ---------------------------------------------------------------------------
__global__ __launch_bounds__(256)
void cvt_bf16_kernel(const float* __restrict__ X, __nv_bfloat16* __restrict__ Y)
{
    const int i = (blockIdx.x * 256 + threadIdx.x) * 4;
    const float4 v = *(const float4*)(X + i);
    __nv_bfloat162 a = __floats2bfloat162_rn(v.x, v.y);
    __nv_bfloat162 b = __floats2bfloat162_rn(v.z, v.w);
    uint2 o; o.x = *(uint32_t*)&a; o.y = *(uint32_t*)&b;
    *(uint2*)(Y + i) = o;
}

// ---------------------------------------------------------------------------
// FA2-style flash attention with raw mma.sync.m16n8k16 (bf16).
// Block = 256 thr (8 warps), q-tile 128 (16 rows/warp), key tile 64.
// S and O live in registers; K/V double-buffered via cp.async; Q frags in regs.
// qkv already has bias. Q pre-scaled by 1/8.
// ---------------------------------------------------------------------------
#define KLD 144            // bytes per smem row (72 bf16)
#define AT_Q  0            // 128 rows
#define AT_K0 (128*KLD)    // 18432
#define AT_V0 (AT_K0 + 64*KLD)
#define AT_K1 (AT_V0 + 64*KLD)
#define AT_V1 (AT_K1 + 64*KLD)
#define AT_SMEM (AT_V1 + 64*KLD)   // 55296

__global__ __launch_bounds__(256, 2)
void attn_mma(const __nv_bfloat16* __restrict__ qkv, __nv_bfloat16* __restrict__ out)
{
    extern __shared__ char sh[];
    const uint32_t sb = smem_u32(sh);
    const int tid = threadIdx.x;
    const int warp = tid >> 5, lane = tid & 31;
    const int q0 = blockIdx.x * 128;
    const int bh = blockIdx.y, b = bh >> 4, h = bh & 15;
    const __nv_bfloat16* base = qkv + (size_t)(b * TT) * D3 + h * DKK;

    // Fill Qs (scale by 1/8; bias already in qkv)
    {
        const __nv_bfloat162 sc = __float2bfloat162_rn(0.125f);
#pragma unroll
        for (int i = 0; i < 4; i++) {
            const int u = tid + i * 256;          // 1024 units of 8 bf16
            const int r = u >> 3, cg = (u & 7) * 8;
            uint4 raw = *(const uint4*)(base + (size_t)(q0 + r) * D3 + cg);
            __nv_bfloat162* pp = (__nv_bfloat162*)&raw;
            pp[0] = __hmul2(pp[0], sc); pp[1] = __hmul2(pp[1], sc);
            pp[2] = __hmul2(pp[2], sc); pp[3] = __hmul2(pp[3], sc);
            *(uint4*)(sh + AT_Q + r * KLD + cg * 2) = raw;
        }
    }
    __syncthreads();

    const int lmat = lane >> 3, lrr = lane & 7;

    // Q fragments (A-operand), 4 k-steps over d=64
    uint32_t qa[4][4];
    {
        const uint32_t qoff = sb + AT_Q +
            (uint32_t)(warp * 16 + (lmat & 1) * 8 + lrr) * KLD + (lmat >> 1) * 16;
#pragma unroll
        for (int kk = 0; kk < 4; kk++)
            ldmx4(qa[kk][0], qa[kk][1], qa[kk][2], qa[kk][3], qoff + kk * 32);
    }

    // ldmatrix per-lane offsets within K/V tiles
    const uint32_t koff = (uint32_t)((lmat >> 1) * 8 + lrr) * KLD + (lmat & 1) * 16;
    const uint32_t voff = (uint32_t)((lmat & 1) * 8 + lrr) * KLD + (lmat >> 1) * 16;

    float oacc[8][4];
#pragma unroll
    for (int nt = 0; nt < 8; nt++)
#pragma unroll
        for (int j = 0; j < 4; j++) oacc[nt][j] = 0.f;
    float m0 = -1e30f, m1 = -1e30f, l0 = 0.f, l1 = 0.f;

    auto issue = [&](int kt, int s) {
        const uint32_t kb = sb + (s ? AT_K1 : AT_K0);
        const uint32_t vb = sb + (s ? AT_V1 : AT_V0);
        const __nv_bfloat16* Kg = base + DD + (size_t)(kt * 64) * D3;
        const __nv_bfloat16* Vg = base + 2 * DD + (size_t)(kt * 64) * D3;
#pragma unroll
        for (int i = 0; i < 2; i++) {
            const int u = tid + i * 256;          // 512 chunks
            const int r = u >> 3, cc = u & 7;
            cp_async16(kb + r * KLD + cc * 16, Kg + (size_t)r * D3 + cc * 8);
        }
#pragma unroll
        for (int i = 0; i < 2; i++) {
            const int u = tid + i * 256;
            const int r = u >> 3, cc = u & 7;
            cp_async16(vb + r * KLD + cc * 16, Vg + (size_t)r * D3 + cc * 8);
        }
        CP_COMMIT();
    };

    issue(0, 0);
    for (int kt = 0; kt < TT / 64; kt++) {
        const int s = kt & 1;
        if (kt + 1 < TT / 64) { issue(kt + 1, (kt + 1) & 1); CP_WAIT(1); }
        else                  { CP_WAIT(0); }
        __syncthreads();

        const uint32_t kb = sb + (s ? AT_K1 : AT_K0);
        const uint32_t vb = sb + (s ? AT_V1 : AT_V0);

        // S = Q @ K^T : n = key (8 tiles of 8), k = d (4 steps of 16)
        float sacc[8][4];
#pragma unroll
        for (int nt = 0; nt < 8; nt++)
#pragma unroll
            for (int j = 0; j < 4; j++) sacc[nt][j] = 0.f;
#pragma unroll
        for (int kk = 0; kk < 4; kk++) {
#pragma unroll
            for (int p = 0; p < 4; p++) {
                uint32_t b0, b1, b2, b3;
                ldmx4(b0, b1, b2, b3, kb + (uint32_t)(p * 16) * KLD + kk * 32 + koff);
                mma16816(sacc[2 * p],     qa[kk], b0, b1);
                mma16816(sacc[2 * p + 1], qa[kk], b2, b3);
            }
        }

        // Online softmax on registers (rows r=lane/4 and r+8)
        float mx0 = -1e30f, mx1 = -1e30f;
#pragma unroll
        for (int nt = 0; nt < 8; nt++) {
            mx0 = fmaxf(mx0, fmaxf(sacc[nt][0], sacc[nt][1]));
            mx1 = fmaxf(mx1, fmaxf(sacc[nt][2], sacc[nt][3]));
        }
        mx0 = fmaxf(mx0, __shfl_xor_sync(0xffffffffu, mx0, 1));
        mx0 = fmaxf(mx0, __shfl_xor_sync(0xffffffffu, mx0, 2));
        mx1 = fmaxf(mx1, __shfl_xor_sync(0xffffffffu, mx1, 1));
        mx1 = fmaxf(mx1, __shfl_xor_sync(0xffffffffu, mx1, 2));
        const float mn0 = fmaxf(m0, mx0), mn1 = fmaxf(m1, mx1);
        const float al0 = __expf(m0 - mn0), al1 = __expf(m1 - mn1);
        float s0 = 0.f, s1 = 0.f;
#pragma unroll
        for (int nt = 0; nt < 8; nt++) {
            sacc[nt][0] = __expf(sacc[nt][0] - mn0); s0 += sacc[nt][0];
            sacc[nt][1] = __expf(sacc[nt][1] - mn0); s0 += sacc[nt][1];
            sacc[nt][2] = __expf(sacc[nt][2] - mn1); s1 += sacc[nt][2];
            sacc[nt][3] = __expf(sacc[nt][3] - mn1); s1 += sacc[nt][3];
        }
        s0 += __shfl_xor_sync(0xffffffffu, s0, 1);
        s0 += __shfl_xor_sync(0xffffffffu, s0, 2);
        s1 += __shfl_xor_sync(0xffffffffu, s1, 1);
        s1 += __shfl_xor_sync(0xffffffffu, s1, 2);
        l0 = l0 * al0 + s0; l1 = l1 * al1 + s1;
        m0 = mn0; m1 = mn1;
#pragma unroll
        for (int nt = 0; nt < 8; nt++) {
            oacc[nt][0] *= al0; oacc[nt][1] *= al0;
            oacc[nt][2] *= al1; oacc[nt][3] *= al1;
        }

        // O += P @ V : k = key (4 steps of 16), n = d (8 tiles of 8)
#pragma unroll
        for (int kk = 0; kk < 4; kk++) {
            uint32_t pa[4];
            pa[0] = bf2pack(sacc[2 * kk][0],     sacc[2 * kk][1]);
            pa[1] = bf2pack(sacc[2 * kk][2],     sacc[2 * kk][3]);
            pa[2] = bf2pack(sacc[2 * kk + 1][0], sacc[2 * kk + 1][1]);
            pa[3] = bf2pack(sacc[2 * kk + 1][2], sacc[2 * kk + 1][3]);
#pragma unroll
            for (int p = 0; p < 4; p++) {
                uint32_t b0, b1, b2, b3;
                ldmx4t(b0, b1, b2, b3, vb + (uint32_t)(kk * 16) * KLD + p * 32 + voff);
                mma16816(oacc[2 * p],     pa, b0, b1);
                mma16816(oacc[2 * p + 1], pa, b2, b3);
            }
        }
        __syncthreads();   // PV reads done before buffer s is refilled
    }

    // Epilogue: O / l -> bf16
    {
        const float i0 = 1.f / l0, i1 = 1.f / l1;
        const size_t r0 = (size_t)(b * TT + q0 + warp * 16 + (lane >> 2)) * DD
                        + h * DKK + (lane & 3) * 2;
        const size_t r1 = r0 + 8 * DD;
#pragma unroll
        for (int nt = 0; nt < 8; nt++) {
            *(uint32_t*)(out + r0 + nt * 8) = bf2pack(oacc[nt][0] * i0, oacc[nt][1] * i0);
            *(uint32_t*)(out + r1 + nt * 8) = bf2pack(oacc[nt][2] * i1, oacc[nt][3] * i1);
        }
    }
}

// ---------------------------------------------------------------------------
// Fused: res = x + C_raw + b_out ; LayerNorm
// ---------------------------------------------------------------------------
__global__ __launch_bounds__(256)
void ln_fused(const float* __restrict__ Craw, const float* __restrict__ x,
              const float* __restrict__ bout, const float* __restrict__ gamma,
              const float* __restrict__ beta, float* __restrict__ Y)
{
    __shared__ float red[8];
    const int row = blockIdx.x;
    const int tid = threadIdx.x;
    const int c = tid * 4;
    const float4 cv = *(const float4*)(Craw + (size_t)row * DD + c);
    const float4 xv = *(const float4*)(x + (size_t)row * DD + c);
    const float4 bv = *(const float4*)(bout + c);
    float4 v;
    v.x = cv.x + xv.x + bv.x;
    v.y = cv.y + xv.y + bv.y;
    v.z = cv.z + xv.z + bv.z;
    v.w = cv.w + xv.w + bv.w;

    float s = v.x + v.y + v.z + v.w;
#pragma unroll
    for (int off = 16; off >= 1; off >>= 1)
        s += __shfl_xor_sync(0xffffffffu, s, off);
    if ((tid & 31) == 0) red[tid >> 5] = s;
    __syncthreads();
    float tot = red[0] + red[1] + red[2] + red[3] + red[4] + red[5] + red[6] + red[7];
    const float mean = tot * (1.f / 1024.f);
    __syncthreads();

    const float dx = v.x - mean, dy = v.y - mean, dz = v.z - mean, dw = v.w - mean;
    float ss = dx * dx + dy * dy + dz * dz + dw * dw;
#pragma unroll
    for (int off = 16; off >= 1; off >>= 1)
        ss += __shfl_xor_sync(0xffffffffu, ss, off);
    if ((tid & 31) == 0) red[tid >> 5] = ss;
    __syncthreads();
    float var = (red[0] + red[1] + red[2] + red[3] + red[4] + red[5] + red[6] + red[7])
                * (1.f / 1024.f);
    const float rstd = rsqrtf(var + 1e-5f);

    const float4 g = *(const float4*)(gamma + c);
    const float4 be = *(const float4*)(beta + c);
    float4 o;
    o.x = dx * rstd * g.x + be.x;
    o.y = dy * rstd * g.y + be.y;
    o.z = dz * rstd * g.z + be.z;
    o.w = dw * rstd * g.w + be.w;
    *(float4*)(Y + (size_t)row * DD + c) = o;
}

// ---------------------------------------------------------------------------
extern "C" void kernel_launch(void* const* d_in, const int* in_sizes, int n_in,
                              void* d_out, int out_size)
{
    const float* x     = (const float*)d_in[0];
    const float* Wqkv  = (const float*)d_in[1];
    const float* bqkv  = (const float*)d_in[2];
    const float* Wout  = (const float*)d_in[3];
    const float* bout  = (const float*)d_in[4];
    const float* gamma = (const float*)d_in[5];
    const float* beta  = (const float*)d_in[6];
    float* out = (float*)d_out;

    __nv_bfloat16 *xb, *wqkv, *wout, *qkv, *att;
    float* res;
    cudaGetSymbolAddress((void**)&xb, g_xb);
    cudaGetSymbolAddress((void**)&wqkv, g_wqkv);
    cudaGetSymbolAddress((void**)&wout, g_wout);
    cudaGetSymbolAddress((void**)&qkv, g_qkv);
    cudaGetSymbolAddress((void**)&att, g_att);
    cudaGetSymbolAddress((void**)&res, g_res);

    cudaFuncSetAttribute(attn_mma, cudaFuncAttributeMaxDynamicSharedMemorySize, AT_SMEM);
    cudaFuncSetAttribute(gemm_wb<true>, cudaFuncAttributeMaxDynamicSharedMemorySize, GEMM_SMEM);
    cudaFuncSetAttribute(gemm_wb<false>, cudaFuncAttributeMaxDynamicSharedMemorySize, GEMM_SMEM);

    // 0. Prep: convert inputs to bf16
    cvt_bf16_kernel<<<NTOK * DD / 1024, 256>>>(x, xb);
    cvt_bf16_kernel<<<DD * D3 / 1024, 256>>>(Wqkv, wqkv);
    cvt_bf16_kernel<<<DD * DD / 1024, 256>>>(Wout, wout);

    // 1. QKV projection + bias (bf16 out)
    {
        dim3 grid(D3 / 128, NTOK / 128);
        gemm_wb<true><<<grid, 256, GEMM_SMEM>>>(xb, wqkv, bqkv, qkv, NTOK, D3, DD);
    }
    // 2. Attention (register-resident FA2, mma.sync)
    {
        dim3 grid(TT / 128, BB * HH);
        attn_mma<<<grid, 256, AT_SMEM>>>(qkv, att);
    }
    // 3. Output projection (fp32 out; bias+residual fused into LN)
    {
        dim3 grid(DD / 128, NTOK / 128);
        gemm_wb<false><<<grid, 256, GEMM_SMEM>>>(att, wout, nullptr, res, NTOK, DD, DD);
    }
    // 4. res = x + C + b_out, then LayerNorm
    ln_fused<<<NTOK, 256>>>(res, x, bout, gamma, beta, out);
}

// round 9
// speedup vs baseline: 11.7727x; 1.0345x over previous
#include <cuda_runtime.h>
#include <cuda_bf16.h>
#include <mma.h>
#include <math.h>
#include <cstdint>

using namespace nvcuda;

#define BB 4
#define TT 2048
#define DD 1024
#define HH 16
#define DKK 64
#define NTOK (BB*TT)      // 8192
#define D3 (3*DD)         // 3072

// Scratch (allocation-free rule: __device__ globals)
__device__ __nv_bfloat16 g_xb[NTOK * DD];      // x bf16
__device__ __nv_bfloat16 g_wqkv[DD * D3];      // W_qkv bf16 row-major
__device__ __nv_bfloat16 g_wout[DD * DD];      // W_out bf16 row-major
__device__ __nv_bfloat16 g_qkv[NTOK * D3];     // QKV bf16 WITH bias
__device__ __nv_bfloat16 g_att[NTOK * DD];     // attention out bf16
__device__ float         g_res[NTOK * DD];     // raw out-proj fp32

__device__ __forceinline__ uint32_t smem_u32(const void* p) {
    uint32_t a;
    asm("{ .reg .u64 t; cvta.to.shared.u64 t, %1; cvt.u32.u64 %0, t; }" : "=r"(a) : "l"(p));
    return a;
}
__device__ __forceinline__ void cp_async16(uint32_t s, const void* g) {
    asm volatile("cp.async.cg.shared.global [%0], [%1], 16;" :: "r"(s), "l"(g) : "memory");
}
#define CP_COMMIT() asm volatile("cp.async.commit_group;" ::: "memory")
#define CP_WAIT(N)  asm volatile("cp.async.wait_group %0;" :: "n"(N) : "memory")

__device__ __forceinline__ uint32_t bf2pack(float x, float y) {
    __nv_bfloat162 p = __floats2bfloat162_rn(x, y);
    return *(uint32_t*)&p;
}
__device__ __forceinline__ void ldmx4(uint32_t& r0, uint32_t& r1, uint32_t& r2,
                                      uint32_t& r3, uint32_t addr) {
    asm volatile("ldmatrix.sync.aligned.m8n8.x4.shared.b16 {%0,%1,%2,%3}, [%4];"
                 : "=r"(r0), "=r"(r1), "=r"(r2), "=r"(r3) : "r"(addr));
}
__device__ __forceinline__ void ldmx4t(uint32_t& r0, uint32_t& r1, uint32_t& r2,
                                       uint32_t& r3, uint32_t addr) {
    asm volatile("ldmatrix.sync.aligned.m8n8.x4.trans.shared.b16 {%0,%1,%2,%3}, [%4];"
                 : "=r"(r0), "=r"(r1), "=r"(r2), "=r"(r3) : "r"(addr));
}
__device__ __forceinline__ void mma16816(float* c, const uint32_t* a,
                                         uint32_t b0, uint32_t b1) {
    asm volatile("mma.sync.aligned.m16n8k16.row.col.f32.bf16.bf16.f32 "
                 "{%0,%1,%2,%3}, {%4,%5,%6,%7}, {%8,%9}, {%0,%1,%2,%3};"
                 : "+f"(c[0]), "+f"(c[1]), "+f"(c[2]), "+f"(c[3])
                 : "r"(a[0]), "r"(a[1]), "r"(a[2]), "r"(a[3]), "r"(b0), "r"(b1));
}

// ---------------------------------------------------------------------------
// 3-stage cp.async bf16 wmma GEMM: C[M,N] = A[M,K] @ B[K,N] (+bias)
// Block tile 128x128, K chunk 64, 256 thr = 8 warps (4x2), warp 32x64.
// ONE __syncthreads per chunk; prefetch distance 2.
// ---------------------------------------------------------------------------
#define ALD_A 72           // bf16 elems per A smem row (144B)
#define ALD_B 136          // bf16 elems per B smem row (272B)
#define STG_A (128*ALD_A*2)              // 18432
#define STG_BYTES (STG_A + 64*ALD_B*2)   // 35840
#define GEMM_SMEM (3*STG_BYTES)          // 107520
#define CLD 132

template<bool BF16_OUT>
__global__ __launch_bounds__(256, 2)
void gemm_wb(const __nv_bfloat16* __restrict__ A, const __nv_bfloat16* __restrict__ B,
             const float* __restrict__ bias, void* __restrict__ Cout,
             int M, int N, int K)
{
    extern __shared__ char sh[];
    const uint32_t sb = smem_u32(sh);
    const int tid = threadIdx.x;
    const int w  = tid >> 5;
    const int wm = w >> 1;
    const int wn = w & 1;
    const int row0 = blockIdx.y * 128;
    const int col0 = blockIdx.x * 128;

    wmma::fragment<wmma::accumulator, 16, 16, 16, float> acc[2][4];
#pragma unroll
    for (int i = 0; i < 2; i++)
#pragma unroll
        for (int j = 0; j < 4; j++) wmma::fill_fragment(acc[i][j], 0.f);

    const int nchunk = K / 64;

    auto issue = [&](int c, int s) {
        const uint32_t aB = sb + s * STG_BYTES;
        const uint32_t bB = aB + STG_A;
        const __nv_bfloat16* Ag = A + (size_t)row0 * K + c * 64;
        const __nv_bfloat16* Bg = B + (size_t)(c * 64) * N + col0;
#pragma unroll
        for (int i = 0; i < 4; i++) {
            const int u = tid + i * 256;
            const int r = u >> 3, cc = u & 7;
            cp_async16(aB + r * (ALD_A * 2) + cc * 16, Ag + (size_t)r * K + cc * 8);
        }
#pragma unroll
        for (int i = 0; i < 4; i++) {
            const int u = tid + i * 256;
            const int r = u >> 4, cc = u & 15;
            cp_async16(bB + r * (ALD_B * 2) + cc * 16, Bg + (size_t)r * N + cc * 8);
        }
        CP_COMMIT();
    };

    issue(0, 0);
    issue(1, 1);
    for (int c = 0; c < nchunk; c++) {
        const int s = c % 3;
        CP_WAIT(1);          // chunk c resident
        __syncthreads();     // also: all warps done reading stage reused below

        const __nv_bfloat16* Asb = (const __nv_bfloat16*)(sh + s * STG_BYTES);
        const __nv_bfloat16* Bsb = (const __nv_bfloat16*)(sh + s * STG_BYTES + STG_A);
#pragma unroll
        for (int ks = 0; ks < 4; ks++) {
            wmma::fragment<wmma::matrix_a, 16, 16, 16, __nv_bfloat16, wmma::row_major> a[2];
            wmma::fragment<wmma::matrix_b, 16, 16, 16, __nv_bfloat16, wmma::row_major> b[4];
#pragma unroll
            for (int i = 0; i < 2; i++)
                wmma::load_matrix_sync(a[i], Asb + (wm * 32 + i * 16) * ALD_A + ks * 16, ALD_A);
#pragma unroll
            for (int j = 0; j < 4; j++)
                wmma::load_matrix_sync(b[j], Bsb + (ks * 16) * ALD_B + wn * 64 + j * 16, ALD_B);
#pragma unroll
            for (int i = 0; i < 2; i++)
#pragma unroll
                for (int j = 0; j < 4; j++)
                    wmma::mma_sync(acc[i][j], a[i], b[j], acc[i][j]);
        }
        if (c + 2 < nchunk) issue(c + 2, (c + 2) % 3);
        else                CP_COMMIT();   // keep group accounting aligned
    }
    __syncthreads();

    if (BF16_OUT) {
        float* Cs = (float*)sh;
#pragma unroll
        for (int i = 0; i < 2; i++)
#pragma unroll
            for (int j = 0; j < 4; j++)
                wmma::store_matrix_sync(Cs + (wm * 32 + i * 16) * CLD + wn * 64 + j * 16,
                                        acc[i][j], CLD, wmma::mem_row_major);
        __syncthreads();
        __nv_bfloat16* C = (__nv_bfloat16*)Cout;
#pragma unroll
        for (int i = 0; i < 8; i++) {
            const int u = tid + i * 256;
            const int r = u >> 4, cg = (u & 15) * 8;
            const float4 bv0 = *(const float4*)(bias + col0 + cg);
            const float4 bv1 = *(const float4*)(bias + col0 + cg + 4);
            const float4 v0 = *(const float4*)(Cs + r * CLD + cg);
            const float4 v1 = *(const float4*)(Cs + r * CLD + cg + 4);
            __nv_bfloat162 p0 = __floats2bfloat162_rn(v0.x + bv0.x, v0.y + bv0.y);
            __nv_bfloat162 p1 = __floats2bfloat162_rn(v0.z + bv0.z, v0.w + bv0.w);
            __nv_bfloat162 p2 = __floats2bfloat162_rn(v1.x + bv1.x, v1.y + bv1.y);
            __nv_bfloat162 p3 = __floats2bfloat162_rn(v1.z + bv1.z, v1.w + bv1.w);
            uint4 o;
            o.x = *(uint32_t*)&p0; o.y = *(uint32_t*)&p1;
            o.z = *(uint32_t*)&p2; o.w = *(uint32_t*)&p3;
            *(uint4*)(C + (size_t)(row0 + r) * N + col0 + cg) = o;
        }
    } else {
        float* C = (float*)Cout;
#pragma unroll
        for (int i = 0; i < 2; i++)
#pragma unroll
            for (int j = 0; j < 4; j++)
                wmma::store_matrix_sync(
                    C + (size_t)(row0 + wm * 32 + i * 16) * N + col0 + wn * 64 + j * 16,
                    acc[i][j], N, wmma::mem_row_major);
    }
}

// ---------------------------------------------------------------------------
// Prep: fp32 -> bf16 convert
// ---------------------------------------------------------------------------
__global__ __launch_bounds__(256)
void cvt_bf16_kernel(const float* __restrict__ X, __nv_bfloat16* __restrict__ Y)
{
    const int i = (blockIdx.x * 256 + threadIdx.x) * 4;
    const float4 v = *(const float4*)(X + i);
    __nv_bfloat162 a = __floats2bfloat162_rn(v.x, v.y);
    __nv_bfloat162 b = __floats2bfloat162_rn(v.z, v.w);
    uint2 o; o.x = *(uint32_t*)&a; o.y = *(uint32_t*)&b;
    *(uint2*)(Y + i) = o;
}

// ---------------------------------------------------------------------------
// FA2 flash attention, mma.sync.m16n8k16 bf16, 3-stage cp.async K/V ring.
// Block = 256 thr (8 warps), q-tile 128 (16 rows/warp), key tile 64.
// ONE __syncthreads per key tile.
// ---------------------------------------------------------------------------
#define KLD 144                 // bytes per smem row (72 bf16)
#define AT_Q  0                 // 128 rows
#define AT_KV (128*KLD)         // ring base: 3 stages x (K 9216 + V 9216)
#define AT_STG (64*KLD*2)       // 18432 per stage
#define AT_SMEM (AT_KV + 3*AT_STG)   // 73728

__global__ __launch_bounds__(256, 2)
void attn_mma(const __nv_bfloat16* __restrict__ qkv, __nv_bfloat16* __restrict__ out)
{
    extern __shared__ char sh[];
    const uint32_t sb = smem_u32(sh);
    const int tid = threadIdx.x;
    const int warp = tid >> 5, lane = tid & 31;
    const int q0 = blockIdx.x * 128;
    const int bh = blockIdx.y, b = bh >> 4, h = bh & 15;
    const __nv_bfloat16* base = qkv + (size_t)(b * TT) * D3 + h * DKK;

    // Fill Qs (scale by 1/8; bias already in qkv)
    {
        const __nv_bfloat162 sc = __float2bfloat162_rn(0.125f);
#pragma unroll
        for (int i = 0; i < 4; i++) {
            const int u = tid + i * 256;
            const int r = u >> 3, cg = (u & 7) * 8;
            uint4 raw = *(const uint4*)(base + (size_t)(q0 + r) * D3 + cg);
            __nv_bfloat162* pp = (__nv_bfloat162*)&raw;
            pp[0] = __hmul2(pp[0], sc); pp[1] = __hmul2(pp[1], sc);
            pp[2] = __hmul2(pp[2], sc); pp[3] = __hmul2(pp[3], sc);
            *(uint4*)(sh + AT_Q + r * KLD + cg * 2) = raw;
        }
    }

    auto issue = [&](int kt, int s) {
        const uint32_t kb = sb + AT_KV + s * AT_STG;
        const uint32_t vb = kb + 64 * KLD;
        const __nv_bfloat16* Kg = base + DD + (size_t)(kt * 64) * D3;
        const __nv_bfloat16* Vg = base + 2 * DD + (size_t)(kt * 64) * D3;
#pragma unroll
        for (int i = 0; i < 2; i++) {
            const int u = tid + i * 256;
            const int r = u >> 3, cc = u & 7;
            cp_async16(kb + r * KLD + cc * 16, Kg + (size_t)r * D3 + cc * 8);
        }
#pragma unroll
        for (int i = 0; i < 2; i++) {
            const int u = tid + i * 256;
            const int r = u >> 3, cc = u & 7;
            cp_async16(vb + r * KLD + cc * 16, Vg + (size_t)r * D3 + cc * 8);
        }
        CP_COMMIT();
    };

    issue(0, 0);
    issue(1, 1);
    __syncthreads();   // Q visible

    const int lmat = lane >> 3, lrr = lane & 7;

    // Q fragments (A-operand), 4 k-steps over d=64
    uint32_t qa[4][4];
    {
        const uint32_t qoff = sb + AT_Q +
            (uint32_t)(warp * 16 + (lmat & 1) * 8 + lrr) * KLD + (lmat >> 1) * 16;
#pragma unroll
        for (int kk = 0; kk < 4; kk++)
            ldmx4(qa[kk][0], qa[kk][1], qa[kk][2], qa[kk][3], qoff + kk * 32);
    }

    const uint32_t koff = (uint32_t)((lmat >> 1) * 8 + lrr) * KLD + (lmat & 1) * 16;
    const uint32_t voff = (uint32_t)((lmat & 1) * 8 + lrr) * KLD + (lmat >> 1) * 16;

    float oacc[8][4];
#pragma unroll
    for (int nt = 0; nt < 8; nt++)
#pragma unroll
        for (int j = 0; j < 4; j++) oacc[nt][j] = 0.f;
    float m0 = -1e30f, m1 = -1e30f, l0 = 0.f, l1 = 0.f;

    for (int kt = 0; kt < TT / 64; kt++) {
        const int s = kt % 3;
        CP_WAIT(1);
        __syncthreads();

        const uint32_t kb = sb + AT_KV + s * AT_STG;
        const uint32_t vb = kb + 64 * KLD;

        // S = Q @ K^T
        float sacc[8][4];
#pragma unroll
        for (int nt = 0; nt < 8; nt++)
#pragma unroll
            for (int j = 0; j < 4; j++) sacc[nt][j] = 0.f;
#pragma unroll
        for (int kk = 0; kk < 4; kk++) {
#pragma unroll
            for (int p = 0; p < 4; p++) {
                uint32_t b0, b1, b2, b3;
                ldmx4(b0, b1, b2, b3, kb + (uint32_t)(p * 16) * KLD + kk * 32 + koff);
                mma16816(sacc[2 * p],     qa[kk], b0, b1);
                mma16816(sacc[2 * p + 1], qa[kk], b2, b3);
            }
        }

        // Online softmax on registers
        float mx0 = -1e30f, mx1 = -1e30f;
#pragma unroll
        for (int nt = 0; nt < 8; nt++) {
            mx0 = fmaxf(mx0, fmaxf(sacc[nt][0], sacc[nt][1]));
            mx1 = fmaxf(mx1, fmaxf(sacc[nt][2], sacc[nt][3]));
        }
        mx0 = fmaxf(mx0, __shfl_xor_sync(0xffffffffu, mx0, 1));
        mx0 = fmaxf(mx0, __shfl_xor_sync(0xffffffffu, mx0, 2));
        mx1 = fmaxf(mx1, __shfl_xor_sync(0xffffffffu, mx1, 1));
        mx1 = fmaxf(mx1, __shfl_xor_sync(0xffffffffu, mx1, 2));
        const float mn0 = fmaxf(m0, mx0), mn1 = fmaxf(m1, mx1);
        const float al0 = __expf(m0 - mn0), al1 = __expf(m1 - mn1);
        float s0 = 0.f, s1 = 0.f;
#pragma unroll
        for (int nt = 0; nt < 8; nt++) {
            sacc[nt][0] = __expf(sacc[nt][0] - mn0); s0 += sacc[nt][0];
            sacc[nt][1] = __expf(sacc[nt][1] - mn0); s0 += sacc[nt][1];
            sacc[nt][2] = __expf(sacc[nt][2] - mn1); s1 += sacc[nt][2];
            sacc[nt][3] = __expf(sacc[nt][3] - mn1); s1 += sacc[nt][3];
        }
        s0 += __shfl_xor_sync(0xffffffffu, s0, 1);
        s0 += __shfl_xor_sync(0xffffffffu, s0, 2);
        s1 += __shfl_xor_sync(0xffffffffu, s1, 1);
        s1 += __shfl_xor_sync(0xffffffffu, s1, 2);
        l0 = l0 * al0 + s0; l1 = l1 * al1 + s1;
        m0 = mn0; m1 = mn1;
#pragma unroll
        for (int nt = 0; nt < 8; nt++) {
            oacc[nt][0] *= al0; oacc[nt][1] *= al0;
            oacc[nt][2] *= al1; oacc[nt][3] *= al1;
        }

        // O += P @ V
#pragma unroll
        for (int kk = 0; kk < 4; kk++) {
            uint32_t pa[4];
            pa[0] = bf2pack(sacc[2 * kk][0],     sacc[2 * kk][1]);
            pa[1] = bf2pack(sacc[2 * kk][2],     sacc[2 * kk][3]);
            pa[2] = bf2pack(sacc[2 * kk + 1][0], sacc[2 * kk + 1][1]);
            pa[3] = bf2pack(sacc[2 * kk + 1][2], sacc[2 * kk + 1][3]);
#pragma unroll
            for (int p = 0; p < 4; p++) {
                uint32_t b0, b1, b2, b3;
                ldmx4t(b0, b1, b2, b3, vb + (uint32_t)(kk * 16) * KLD + p * 32 + voff);
                mma16816(oacc[2 * p],     pa, b0, b1);
                mma16816(oacc[2 * p + 1], pa, b2, b3);
            }
        }
        if (kt + 2 < TT / 64) issue(kt + 2, (kt + 2) % 3);
        else                  CP_COMMIT();
    }

    // Epilogue: O / l -> bf16
    {
        const float i0 = 1.f / l0, i1 = 1.f / l1;
        const size_t r0 = (size_t)(b * TT + q0 + warp * 16 + (lane >> 2)) * DD
                        + h * DKK + (lane & 3) * 2;
        const size_t r1 = r0 + 8 * DD;
#pragma unroll
        for (int nt = 0; nt < 8; nt++) {
            *(uint32_t*)(out + r0 + nt * 8) = bf2pack(oacc[nt][0] * i0, oacc[nt][1] * i0);
            *(uint32_t*)(out + r1 + nt * 8) = bf2pack(oacc[nt][2] * i1, oacc[nt][3] * i1);
        }
    }
}

// ---------------------------------------------------------------------------
// Fused: res = x + C_raw + b_out ; LayerNorm
// ---------------------------------------------------------------------------
__global__ __launch_bounds__(256)
void ln_fused(const float* __restrict__ Craw, const float* __restrict__ x,
              const float* __restrict__ bout, const float* __restrict__ gamma,
              const float* __restrict__ beta, float* __restrict__ Y)
{
    __shared__ float red[8];
    const int row = blockIdx.x;
    const int tid = threadIdx.x;
    const int c = tid * 4;
    const float4 cv = *(const float4*)(Craw + (size_t)row * DD + c);
    const float4 xv = *(const float4*)(x + (size_t)row * DD + c);
    const float4 bv = *(const float4*)(bout + c);
    float4 v;
    v.x = cv.x + xv.x + bv.x;
    v.y = cv.y + xv.y + bv.y;
    v.z = cv.z + xv.z + bv.z;
    v.w = cv.w + xv.w + bv.w;

    float s = v.x + v.y + v.z + v.w;
#pragma unroll
    for (int off = 16; off >= 1; off >>= 1)
        s += __shfl_xor_sync(0xffffffffu, s, off);
    if ((tid & 31) == 0) red[tid >> 5] = s;
    __syncthreads();
    float tot = red[0] + red[1] + red[2] + red[3] + red[4] + red[5] + red[6] + red[7];
    const float mean = tot * (1.f / 1024.f);
    __syncthreads();

    const float dx = v.x - mean, dy = v.y - mean, dz = v.z - mean, dw = v.w - mean;
    float ss = dx * dx + dy * dy + dz * dz + dw * dw;
#pragma unroll
    for (int off = 16; off >= 1; off >>= 1)
        ss += __shfl_xor_sync(0xffffffffu, ss, off);
    if ((tid & 31) == 0) red[tid >> 5] = ss;
    __syncthreads();
    float var = (red[0] + red[1] + red[2] + red[3] + red[4] + red[5] + red[6] + red[7])
                * (1.f / 1024.f);
    const float rstd = rsqrtf(var + 1e-5f);

    const float4 g = *(const float4*)(gamma + c);
    const float4 be = *(const float4*)(beta + c);
    float4 o;
    o.x = dx * rstd * g.x + be.x;
    o.y = dy * rstd * g.y + be.y;
    o.z = dz * rstd * g.z + be.z;
    o.w = dw * rstd * g.w + be.w;
    *(float4*)(Y + (size_t)row * DD + c) = o;
}

// ---------------------------------------------------------------------------
extern "C" void kernel_launch(void* const* d_in, const int* in_sizes, int n_in,
                              void* d_out, int out_size)
{
    const float* x     = (const float*)d_in[0];
    const float* Wqkv  = (const float*)d_in[1];
    const float* bqkv  = (const float*)d_in[2];
    const float* Wout  = (const float*)d_in[3];
    const float* bout  = (const float*)d_in[4];
    const float* gamma = (const float*)d_in[5];
    const float* beta  = (const float*)d_in[6];
    float* out = (float*)d_out;

    __nv_bfloat16 *xb, *wqkv, *wout, *qkv, *att;
    float* res;
    cudaGetSymbolAddress((void**)&xb, g_xb);
    cudaGetSymbolAddress((void**)&wqkv, g_wqkv);
    cudaGetSymbolAddress((void**)&wout, g_wout);
    cudaGetSymbolAddress((void**)&qkv, g_qkv);
    cudaGetSymbolAddress((void**)&att, g_att);
    cudaGetSymbolAddress((void**)&res, g_res);

    cudaFuncSetAttribute(attn_mma, cudaFuncAttributeMaxDynamicSharedMemorySize, AT_SMEM);
    cudaFuncSetAttribute(gemm_wb<true>, cudaFuncAttributeMaxDynamicSharedMemorySize, GEMM_SMEM);
    cudaFuncSetAttribute(gemm_wb<false>, cudaFuncAttributeMaxDynamicSharedMemorySize, GEMM_SMEM);

    // 0. Prep: convert inputs to bf16
    cvt_bf16_kernel<<<NTOK * DD / 1024, 256>>>(x, xb);
    cvt_bf16_kernel<<<DD * D3 / 1024, 256>>>(Wqkv, wqkv);
    cvt_bf16_kernel<<<DD * DD / 1024, 256>>>(Wout, wout);

    // 1. QKV projection + bias (bf16 out)
    {
        dim3 grid(D3 / 128, NTOK / 128);
        gemm_wb<true><<<grid, 256, GEMM_SMEM>>>(xb, wqkv, bqkv, qkv, NTOK, D3, DD);
    }
    // 2. Attention (register-resident FA2, mma.sync, ring-3 pipeline)
    {
        dim3 grid(TT / 128, BB * HH);
        attn_mma<<<grid, 256, AT_SMEM>>>(qkv, att);
    }
    // 3. Output projection (fp32 out; bias+residual fused into LN)
    {
        dim3 grid(DD / 128, NTOK / 128);
        gemm_wb<false><<<grid, 256, GEMM_SMEM>>>(att, wout, nullptr, res, NTOK, DD, DD);
    }
    // 4. res = x + C + b_out, then LayerNorm
    ln_fused<<<NTOK, 256>>>(res, x, bout, gamma, beta, out);
}

// round 10
// speedup vs baseline: 14.1194x; 1.1993x over previous
#include <cuda_runtime.h>
#include <cuda_bf16.h>
#include <math.h>
#include <cstdint>

#define BB 4
#define TT 2048
#define DD 1024
#define HH 16
#define DKK 64
#define NTOK (BB*TT)      // 8192
#define D3 (3*DD)         // 3072

// Scratch (allocation-free rule: __device__ globals)
__device__ __nv_bfloat16 g_xb[NTOK * DD];
__device__ __nv_bfloat16 g_wqkv[DD * D3];
__device__ __nv_bfloat16 g_wout[DD * DD];
__device__ __nv_bfloat16 g_qkv[NTOK * D3];     // QKV bf16 WITH bias
__device__ __nv_bfloat16 g_att[NTOK * DD];
__device__ float         g_res[NTOK * DD];

__device__ __forceinline__ uint32_t smem_u32(const void* p) {
    uint32_t a;
    asm("{ .reg .u64 t; cvta.to.shared.u64 t, %1; cvt.u32.u64 %0, t; }" : "=r"(a) : "l"(p));
    return a;
}
__device__ __forceinline__ void cp_async16(uint32_t s, const void* g) {
    asm volatile("cp.async.cg.shared.global [%0], [%1], 16;" :: "r"(s), "l"(g) : "memory");
}
#define CP_COMMIT() asm volatile("cp.async.commit_group;" ::: "memory")
#define CP_WAIT(N)  asm volatile("cp.async.wait_group %0;" :: "n"(N) : "memory")

__device__ __forceinline__ uint32_t bf2pack(float x, float y) {
    __nv_bfloat162 p = __floats2bfloat162_rn(x, y);
    return *(uint32_t*)&p;
}
__device__ __forceinline__ void ldmx4(uint32_t* r, uint32_t addr) {
    asm volatile("ldmatrix.sync.aligned.m8n8.x4.shared.b16 {%0,%1,%2,%3}, [%4];"
                 : "=r"(r[0]), "=r"(r[1]), "=r"(r[2]), "=r"(r[3]) : "r"(addr));
}
__device__ __forceinline__ void ldmx4t(uint32_t* r, uint32_t addr) {
    asm volatile("ldmatrix.sync.aligned.m8n8.x4.trans.shared.b16 {%0,%1,%2,%3}, [%4];"
                 : "=r"(r[0]), "=r"(r[1]), "=r"(r[2]), "=r"(r[3]) : "r"(addr));
}
__device__ __forceinline__ void mma16816(float* c, const uint32_t* a,
                                         uint32_t b0, uint32_t b1) {
    asm volatile("mma.sync.aligned.m16n8k16.row.col.f32.bf16.bf16.f32 "
                 "{%0,%1,%2,%3}, {%4,%5,%6,%7}, {%8,%9}, {%0,%1,%2,%3};"
                 : "+f"(c[0]), "+f"(c[1]), "+f"(c[2]), "+f"(c[3])
                 : "r"(a[0]), "r"(a[1]), "r"(a[2]), "r"(a[3]), "r"(b0), "r"(b1));
}

// ---------------------------------------------------------------------------
// Raw-mma bf16 GEMM, 3-stage cp.async ring, register double-buffered frags.
// C[M,N] = A[M,K] @ B[K,N] (+bias). Block 128x128, K chunk 64, 8 warps (4x2),
// warp tile 32x64.
// ---------------------------------------------------------------------------
#define ALD_A 72           // bf16 elems per A smem row (144B)
#define ALD_B 136          // bf16 elems per B smem row (272B)
#define STG_A (128*ALD_A*2)              // 18432
#define STG_BYTES (STG_A + 64*ALD_B*2)   // 35840
#define GEMM_SMEM (3*STG_BYTES)          // 107520
#define CLD 132

template<bool BF16_OUT>
__global__ __launch_bounds__(256, 2)
void gemm_mma(const __nv_bfloat16* __restrict__ A, const __nv_bfloat16* __restrict__ B,
              const float* __restrict__ bias, void* __restrict__ Cout,
              int M, int N, int K)
{
    extern __shared__ char sh[];
    const uint32_t sb = smem_u32(sh);
    const int tid = threadIdx.x;
    const int w = tid >> 5, lane = tid & 31;
    const int wm = w >> 1, wn = w & 1;
    const int lmat = lane >> 3, lrr = lane & 7;
    const int row0 = blockIdx.y * 128;
    const int col0 = blockIdx.x * 128;

    float acc[2][8][4];
#pragma unroll
    for (int i = 0; i < 2; i++)
#pragma unroll
        for (int nt = 0; nt < 8; nt++)
#pragma unroll
            for (int j = 0; j < 4; j++) acc[i][nt][j] = 0.f;

    const int nchunk = K / 64;

    auto issue = [&](int c, int s) {
        const uint32_t aB = sb + s * STG_BYTES;
        const uint32_t bB = aB + STG_A;
        const __nv_bfloat16* Ag = A + (size_t)row0 * K + c * 64;
        const __nv_bfloat16* Bg = B + (size_t)(c * 64) * N + col0;
#pragma unroll
        for (int i = 0; i < 4; i++) {
            const int u = tid + i * 256;
            const int r = u >> 3, cc = u & 7;
            cp_async16(aB + r * (ALD_A * 2) + cc * 16, Ag + (size_t)r * K + cc * 8);
        }
#pragma unroll
        for (int i = 0; i < 4; i++) {
            const int u = tid + i * 256;
            const int r = u >> 4, cc = u & 15;
            cp_async16(bB + r * (ALD_B * 2) + cc * 16, Bg + (size_t)r * N + cc * 8);
        }
        CP_COMMIT();
    };

    // fragment lane-base offsets (A: non-trans ldmatrix; B: trans ldmatrix)
    const uint32_t a_base = (uint32_t)(wm * 32 + (lmat & 1) * 8 + lrr) * (ALD_A * 2)
                          + (lmat >> 1) * 16;
    const uint32_t b_base = (uint32_t)((lmat & 1) * 8 + lrr) * (ALD_B * 2)
                          + wn * 128 + (lmat >> 1) * 16;

    uint32_t af[2][2][4];   // [buf][mi][4]
    uint32_t bfr[2][4][4];  // [buf][p][4]

    issue(0, 0);
    issue(1, 1);
    for (int c = 0; c < nchunk; c++) {
        const int s = c % 3;
        CP_WAIT(1);
        __syncthreads();
        const uint32_t aS = sb + s * STG_BYTES;
        const uint32_t bS = aS + STG_A;

        // preload ks=0 fragments
        {
            const uint32_t aadr = aS + a_base;
            ldmx4(af[0][0], aadr);
            ldmx4(af[0][1], aadr + 16 * (ALD_A * 2));
            const uint32_t badr = bS + b_base;
#pragma unroll
            for (int p = 0; p < 4; p++) ldmx4t(bfr[0][p], badr + p * 32);
        }
#pragma unroll
        for (int ks = 0; ks < 4; ks++) {
            const int cur = ks & 1;
            if (ks < 3) {
                const uint32_t aadr = aS + a_base + (ks + 1) * 32;
                ldmx4(af[cur ^ 1][0], aadr);
                ldmx4(af[cur ^ 1][1], aadr + 16 * (ALD_A * 2));
                const uint32_t badr = bS + b_base + (uint32_t)((ks + 1) * 16) * (ALD_B * 2);
#pragma unroll
                for (int p = 0; p < 4; p++) ldmx4t(bfr[cur ^ 1][p], badr + p * 32);
            }
#pragma unroll
            for (int p = 0; p < 4; p++) {
                mma16816(acc[0][2 * p],     af[cur][0], bfr[cur][p][0], bfr[cur][p][1]);
                mma16816(acc[0][2 * p + 1], af[cur][0], bfr[cur][p][2], bfr[cur][p][3]);
                mma16816(acc[1][2 * p],     af[cur][1], bfr[cur][p][0], bfr[cur][p][1]);
                mma16816(acc[1][2 * p + 1], af[cur][1], bfr[cur][p][2], bfr[cur][p][3]);
            }
        }
        if (c + 2 < nchunk) issue(c + 2, (c + 2) % 3);
        else                CP_COMMIT();
    }
    __syncthreads();

    // Stage fp32 result in smem
    {
        float* Cs = (float*)sh;
        const int r = wm * 32 + (lane >> 2);
        const int cb = wn * 64 + (lane & 3) * 2;
#pragma unroll
        for (int i = 0; i < 2; i++)
#pragma unroll
            for (int nt = 0; nt < 8; nt++) {
                *(float2*)&Cs[(r + i * 16) * CLD + cb + nt * 8] =
                    make_float2(acc[i][nt][0], acc[i][nt][1]);
                *(float2*)&Cs[(r + i * 16 + 8) * CLD + cb + nt * 8] =
                    make_float2(acc[i][nt][2], acc[i][nt][3]);
            }
    }
    __syncthreads();

    const float* Cs = (const float*)sh;
    if (BF16_OUT) {
        __nv_bfloat16* C = (__nv_bfloat16*)Cout;
#pragma unroll
        for (int i = 0; i < 8; i++) {
            const int u = tid + i * 256;
            const int r = u >> 4, cg = (u & 15) * 8;
            const float4 bv0 = *(const float4*)(bias + col0 + cg);
            const float4 bv1 = *(const float4*)(bias + col0 + cg + 4);
            const float4 v0 = *(const float4*)(Cs + r * CLD + cg);
            const float4 v1 = *(const float4*)(Cs + r * CLD + cg + 4);
            __nv_bfloat162 p0 = __floats2bfloat162_rn(v0.x + bv0.x, v0.y + bv0.y);
            __nv_bfloat162 p1 = __floats2bfloat162_rn(v0.z + bv0.z, v0.w + bv0.w);
            __nv_bfloat162 p2 = __floats2bfloat162_rn(v1.x + bv1.x, v1.y + bv1.y);
            __nv_bfloat162 p3 = __floats2bfloat162_rn(v1.z + bv1.z, v1.w + bv1.w);
            uint4 o;
            o.x = *(uint32_t*)&p0; o.y = *(uint32_t*)&p1;
            o.z = *(uint32_t*)&p2; o.w = *(uint32_t*)&p3;
            *(uint4*)(C + (size_t)(row0 + r) * N + col0 + cg) = o;
        }
    } else {
        float* C = (float*)Cout;
#pragma unroll
        for (int i = 0; i < 16; i++) {
            const int u = tid + i * 256;
            const int r = u >> 5, cg = (u & 31) * 4;
            const float4 v = *(const float4*)(Cs + r * CLD + cg);
            *(float4*)(C + (size_t)(row0 + r) * N + col0 + cg) = v;
        }
    }
}

// ---------------------------------------------------------------------------
// Prep: fp32 -> bf16 convert
// ---------------------------------------------------------------------------
__global__ __launch_bounds__(256)
void cvt_bf16_kernel(const float* __restrict__ X, __nv_bfloat16* __restrict__ Y)
{
    const int i = (blockIdx.x * 256 + threadIdx.x) * 4;
    const float4 v = *(const float4*)(X + i);
    __nv_bfloat162 a = __floats2bfloat162_rn(v.x, v.y);
    __nv_bfloat162 b = __floats2bfloat162_rn(v.z, v.w);
    uint2 o; o.x = *(uint32_t*)&a; o.y = *(uint32_t*)&b;
    *(uint2*)(Y + i) = o;
}

// ---------------------------------------------------------------------------
// FA2 flash attention, mma.sync bf16, ring-3 cp.async, frag prefetch.
// ---------------------------------------------------------------------------
#define KLD 144
#define AT_Q  0
#define AT_KV (128*KLD)
#define AT_STG (64*KLD*2)
#define AT_SMEM (AT_KV + 3*AT_STG)   // 73728

__global__ __launch_bounds__(256, 2)
void attn_mma(const __nv_bfloat16* __restrict__ qkv, __nv_bfloat16* __restrict__ out)
{
    extern __shared__ char sh[];
    const uint32_t sb = smem_u32(sh);
    const int tid = threadIdx.x;
    const int warp = tid >> 5, lane = tid & 31;
    const int q0 = blockIdx.x * 128;
    const int bh = blockIdx.y, b = bh >> 4, h = bh & 15;
    const __nv_bfloat16* base = qkv + (size_t)(b * TT) * D3 + h * DKK;

    {
        const __nv_bfloat162 sc = __float2bfloat162_rn(0.125f);
#pragma unroll
        for (int i = 0; i < 4; i++) {
            const int u = tid + i * 256;
            const int r = u >> 3, cg = (u & 7) * 8;
            uint4 raw = *(const uint4*)(base + (size_t)(q0 + r) * D3 + cg);
            __nv_bfloat162* pp = (__nv_bfloat162*)&raw;
            pp[0] = __hmul2(pp[0], sc); pp[1] = __hmul2(pp[1], sc);
            pp[2] = __hmul2(pp[2], sc); pp[3] = __hmul2(pp[3], sc);
            *(uint4*)(sh + AT_Q + r * KLD + cg * 2) = raw;
        }
    }

    auto issue = [&](int kt, int s) {
        const uint32_t kb = sb + AT_KV + s * AT_STG;
        const uint32_t vb = kb + 64 * KLD;
        const __nv_bfloat16* Kg = base + DD + (size_t)(kt * 64) * D3;
        const __nv_bfloat16* Vg = base + 2 * DD + (size_t)(kt * 64) * D3;
#pragma unroll
        for (int i = 0; i < 2; i++) {
            const int u = tid + i * 256;
            const int r = u >> 3, cc = u & 7;
            cp_async16(kb + r * KLD + cc * 16, Kg + (size_t)r * D3 + cc * 8);
        }
#pragma unroll
        for (int i = 0; i < 2; i++) {
            const int u = tid + i * 256;
            const int r = u >> 3, cc = u & 7;
            cp_async16(vb + r * KLD + cc * 16, Vg + (size_t)r * D3 + cc * 8);
        }
        CP_COMMIT();
    };

    issue(0, 0);
    issue(1, 1);
    __syncthreads();

    const int lmat = lane >> 3, lrr = lane & 7;

    uint32_t qa[4][4];
    {
        const uint32_t qoff = sb + AT_Q +
            (uint32_t)(warp * 16 + (lmat & 1) * 8 + lrr) * KLD + (lmat >> 1) * 16;
#pragma unroll
        for (int kk = 0; kk < 4; kk++) ldmx4(qa[kk], qoff + kk * 32);
    }

    const uint32_t koff = (uint32_t)((lmat >> 1) * 8 + lrr) * KLD + (lmat & 1) * 16;
    const uint32_t voff = (uint32_t)((lmat & 1) * 8 + lrr) * KLD + (lmat >> 1) * 16;

    float oacc[8][4];
#pragma unroll
    for (int nt = 0; nt < 8; nt++)
#pragma unroll
        for (int j = 0; j < 4; j++) oacc[nt][j] = 0.f;
    float m0 = -1e30f, m1 = -1e30f, l0 = 0.f, l1 = 0.f;

    for (int kt = 0; kt < TT / 64; kt++) {
        const int s = kt % 3;
        CP_WAIT(1);
        __syncthreads();

        const uint32_t kb = sb + AT_KV + s * AT_STG;
        const uint32_t vb = kb + 64 * KLD;

        // S = Q @ K^T with K-frag double buffer over kk
        float sacc[8][4];
#pragma unroll
        for (int nt = 0; nt < 8; nt++)
#pragma unroll
            for (int j = 0; j < 4; j++) sacc[nt][j] = 0.f;

        uint32_t kf[2][4][4];   // [buf][p][4]
#pragma unroll
        for (int p = 0; p < 4; p++)
            ldmx4(kf[0][p], kb + (uint32_t)(p * 16) * KLD + koff);
#pragma unroll
        for (int kk = 0; kk < 4; kk++) {
            const int cur = kk & 1;
            if (kk < 3) {
#pragma unroll
                for (int p = 0; p < 4; p++)
                    ldmx4(kf[cur ^ 1][p], kb + (uint32_t)(p * 16) * KLD + (kk + 1) * 32 + koff);
            }
#pragma unroll
            for (int p = 0; p < 4; p++) {
                mma16816(sacc[2 * p],     qa[kk], kf[cur][p][0], kf[cur][p][1]);
                mma16816(sacc[2 * p + 1], qa[kk], kf[cur][p][2], kf[cur][p][3]);
            }
        }

        // Online softmax on registers
        float mx0 = -1e30f, mx1 = -1e30f;
#pragma unroll
        for (int nt = 0; nt < 8; nt++) {
            mx0 = fmaxf(mx0, fmaxf(sacc[nt][0], sacc[nt][1]));
            mx1 = fmaxf(mx1, fmaxf(sacc[nt][2], sacc[nt][3]));
        }
        mx0 = fmaxf(mx0, __shfl_xor_sync(0xffffffffu, mx0, 1));
        mx0 = fmaxf(mx0, __shfl_xor_sync(0xffffffffu, mx0, 2));
        mx1 = fmaxf(mx1, __shfl_xor_sync(0xffffffffu, mx1, 1));
        mx1 = fmaxf(mx1, __shfl_xor_sync(0xffffffffu, mx1, 2));
        const float mn0 = fmaxf(m0, mx0), mn1 = fmaxf(m1, mx1);
        const float al0 = __expf(m0 - mn0), al1 = __expf(m1 - mn1);
        float s0 = 0.f, s1 = 0.f;
#pragma unroll
        for (int nt = 0; nt < 8; nt++) {
            sacc[nt][0] = __expf(sacc[nt][0] - mn0); s0 += sacc[nt][0];
            sacc[nt][1] = __expf(sacc[nt][1] - mn0); s0 += sacc[nt][1];
            sacc[nt][2] = __expf(sacc[nt][2] - mn1); s1 += sacc[nt][2];
            sacc[nt][3] = __expf(sacc[nt][3] - mn1); s1 += sacc[nt][3];
        }
        s0 += __shfl_xor_sync(0xffffffffu, s0, 1);
        s0 += __shfl_xor_sync(0xffffffffu, s0, 2);
        s1 += __shfl_xor_sync(0xffffffffu, s1, 1);
        s1 += __shfl_xor_sync(0xffffffffu, s1, 2);
        l0 = l0 * al0 + s0; l1 = l1 * al1 + s1;
        m0 = mn0; m1 = mn1;
#pragma unroll
        for (int nt = 0; nt < 8; nt++) {
            oacc[nt][0] *= al0; oacc[nt][1] *= al0;
            oacc[nt][2] *= al1; oacc[nt][3] *= al1;
        }

        // O += P @ V with V-frag double buffer over kk
        uint32_t vf[2][4][4];
#pragma unroll
        for (int p = 0; p < 4; p++)
            ldmx4t(vf[0][p], vb + p * 32 + voff);
#pragma unroll
        for (int kk = 0; kk < 4; kk++) {
            const int cur = kk & 1;
            if (kk < 3) {
#pragma unroll
                for (int p = 0; p < 4; p++)
                    ldmx4t(vf[cur ^ 1][p], vb + (uint32_t)((kk + 1) * 16) * KLD + p * 32 + voff);
            }
            uint32_t pa[4];
            pa[0] = bf2pack(sacc[2 * kk][0],     sacc[2 * kk][1]);
            pa[1] = bf2pack(sacc[2 * kk][2],     sacc[2 * kk][3]);
            pa[2] = bf2pack(sacc[2 * kk + 1][0], sacc[2 * kk + 1][1]);
            pa[3] = bf2pack(sacc[2 * kk + 1][2], sacc[2 * kk + 1][3]);
#pragma unroll
            for (int p = 0; p < 4; p++) {
                mma16816(oacc[2 * p],     pa, vf[cur][p][0], vf[cur][p][1]);
                mma16816(oacc[2 * p + 1], pa, vf[cur][p][2], vf[cur][p][3]);
            }
        }
        if (kt + 2 < TT / 64) issue(kt + 2, (kt + 2) % 3);
        else                  CP_COMMIT();
    }

    // Epilogue: O / l -> bf16
    {
        const float i0 = 1.f / l0, i1 = 1.f / l1;
        const size_t r0 = (size_t)(b * TT + q0 + warp * 16 + (lane >> 2)) * DD
                        + h * DKK + (lane & 3) * 2;
        const size_t r1 = r0 + 8 * DD;
#pragma unroll
        for (int nt = 0; nt < 8; nt++) {
            *(uint32_t*)(out + r0 + nt * 8) = bf2pack(oacc[nt][0] * i0, oacc[nt][1] * i0);
            *(uint32_t*)(out + r1 + nt * 8) = bf2pack(oacc[nt][2] * i1, oacc[nt][3] * i1);
        }
    }
}

// ---------------------------------------------------------------------------
// Fused: res = x + C_raw + b_out ; LayerNorm
// ---------------------------------------------------------------------------
__global__ __launch_bounds__(256)
void ln_fused(const float* __restrict__ Craw, const float* __restrict__ x,
              const float* __restrict__ bout, const float* __restrict__ gamma,
              const float* __restrict__ beta, float* __restrict__ Y)
{
    __shared__ float red[8];
    const int row = blockIdx.x;
    const int tid = threadIdx.x;
    const int c = tid * 4;
    const float4 cv = *(const float4*)(Craw + (size_t)row * DD + c);
    const float4 xv = *(const float4*)(x + (size_t)row * DD + c);
    const float4 bv = *(const float4*)(bout + c);
    float4 v;
    v.x = cv.x + xv.x + bv.x;
    v.y = cv.y + xv.y + bv.y;
    v.z = cv.z + xv.z + bv.z;
    v.w = cv.w + xv.w + bv.w;

    float s = v.x + v.y + v.z + v.w;
#pragma unroll
    for (int off = 16; off >= 1; off >>= 1)
        s += __shfl_xor_sync(0xffffffffu, s, off);
    if ((tid & 31) == 0) red[tid >> 5] = s;
    __syncthreads();
    float tot = red[0] + red[1] + red[2] + red[3] + red[4] + red[5] + red[6] + red[7];
    const float mean = tot * (1.f / 1024.f);
    __syncthreads();

    const float dx = v.x - mean, dy = v.y - mean, dz = v.z - mean, dw = v.w - mean;
    float ss = dx * dx + dy * dy + dz * dz + dw * dw;
#pragma unroll
    for (int off = 16; off >= 1; off >>= 1)
        ss += __shfl_xor_sync(0xffffffffu, ss, off);
    if ((tid & 31) == 0) red[tid >> 5] = ss;
    __syncthreads();
    float var = (red[0] + red[1] + red[2] + red[3] + red[4] + red[5] + red[6] + red[7])
                * (1.f / 1024.f);
    const float rstd = rsqrtf(var + 1e-5f);

    const float4 g = *(const float4*)(gamma + c);
    const float4 be = *(const float4*)(beta + c);
    float4 o;
    o.x = dx * rstd * g.x + be.x;
    o.y = dy * rstd * g.y + be.y;
    o.z = dz * rstd * g.z + be.z;
    o.w = dw * rstd * g.w + be.w;
    *(float4*)(Y + (size_t)row * DD + c) = o;
}

// ---------------------------------------------------------------------------
extern "C" void kernel_launch(void* const* d_in, const int* in_sizes, int n_in,
                              void* d_out, int out_size)
{
    const float* x     = (const float*)d_in[0];
    const float* Wqkv  = (const float*)d_in[1];
    const float* bqkv  = (const float*)d_in[2];
    const float* Wout  = (const float*)d_in[3];
    const float* bout  = (const float*)d_in[4];
    const float* gamma = (const float*)d_in[5];
    const float* beta  = (const float*)d_in[6];
    float* out = (float*)d_out;

    __nv_bfloat16 *xb, *wqkv, *wout, *qkv, *att;
    float* res;
    cudaGetSymbolAddress((void**)&xb, g_xb);
    cudaGetSymbolAddress((void**)&wqkv, g_wqkv);
    cudaGetSymbolAddress((void**)&wout, g_wout);
    cudaGetSymbolAddress((void**)&qkv, g_qkv);
    cudaGetSymbolAddress((void**)&att, g_att);
    cudaGetSymbolAddress((void**)&res, g_res);

    cudaFuncSetAttribute(attn_mma, cudaFuncAttributeMaxDynamicSharedMemorySize, AT_SMEM);
    cudaFuncSetAttribute(gemm_mma<true>, cudaFuncAttributeMaxDynamicSharedMemorySize, GEMM_SMEM);
    cudaFuncSetAttribute(gemm_mma<false>, cudaFuncAttributeMaxDynamicSharedMemorySize, GEMM_SMEM);

    // 0. Prep: convert inputs to bf16
    cvt_bf16_kernel<<<NTOK * DD / 1024, 256>>>(x, xb);
    cvt_bf16_kernel<<<DD * D3 / 1024, 256>>>(Wqkv, wqkv);
    cvt_bf16_kernel<<<DD * DD / 1024, 256>>>(Wout, wout);

    // 1. QKV projection + bias (bf16 out)
    {
        dim3 grid(D3 / 128, NTOK / 128);
        gemm_mma<true><<<grid, 256, GEMM_SMEM>>>(xb, wqkv, bqkv, qkv, NTOK, D3, DD);
    }
    // 2. Attention (register-resident FA2, frag prefetch)
    {
        dim3 grid(TT / 128, BB * HH);
        attn_mma<<<grid, 256, AT_SMEM>>>(qkv, att);
    }
    // 3. Output projection (fp32 out; bias+residual fused into LN)
    {
        dim3 grid(DD / 128, NTOK / 128);
        gemm_mma<false><<<grid, 256, GEMM_SMEM>>>(att, wout, nullptr, res, NTOK, DD, DD);
    }
    // 4. res = x + C + b_out, then LayerNorm
    ln_fused<<<NTOK, 256>>>(res, x, bout, gamma, beta, out);
}

// round 11
// speedup vs baseline: 14.4361x; 1.0224x over previous
#include <cuda_runtime.h>
#include <cuda_bf16.h>
#include <math.h>
#include <cstdint>

#define BB 4
#define TT 2048
#define DD 1024
#define HH 16
#define DKK 64
#define NTOK (BB*TT)      // 8192
#define D3 (3*DD)         // 3072

// Scratch (allocation-free rule: __device__ globals)
__device__ __nv_bfloat16 g_xb[NTOK * DD];
__device__ __nv_bfloat16 g_wqkv[DD * D3];
__device__ __nv_bfloat16 g_wout[DD * DD];
__device__ __nv_bfloat16 g_qkv[NTOK * D3];     // QKV bf16 WITH bias
__device__ __nv_bfloat16 g_att[NTOK * DD];
__device__ float         g_res[NTOK * DD];

__device__ __forceinline__ uint32_t smem_u32(const void* p) {
    uint32_t a;
    asm("{ .reg .u64 t; cvta.to.shared.u64 t, %1; cvt.u32.u64 %0, t; }" : "=r"(a) : "l"(p));
    return a;
}
__device__ __forceinline__ void cp_async16(uint32_t s, const void* g) {
    asm volatile("cp.async.cg.shared.global [%0], [%1], 16;" :: "r"(s), "l"(g) : "memory");
}
#define CP_COMMIT() asm volatile("cp.async.commit_group;" ::: "memory")
#define CP_WAIT(N)  asm volatile("cp.async.wait_group %0;" :: "n"(N) : "memory")

__device__ __forceinline__ uint32_t bf2pack(float x, float y) {
    __nv_bfloat162 p = __floats2bfloat162_rn(x, y);
    return *(uint32_t*)&p;
}
__device__ __forceinline__ void ldmx4(uint32_t* r, uint32_t addr) {
    asm volatile("ldmatrix.sync.aligned.m8n8.x4.shared.b16 {%0,%1,%2,%3}, [%4];"
                 : "=r"(r[0]), "=r"(r[1]), "=r"(r[2]), "=r"(r[3]) : "r"(addr));
}
__device__ __forceinline__ void ldmx4t(uint32_t* r, uint32_t addr) {
    asm volatile("ldmatrix.sync.aligned.m8n8.x4.trans.shared.b16 {%0,%1,%2,%3}, [%4];"
                 : "=r"(r[0]), "=r"(r[1]), "=r"(r[2]), "=r"(r[3]) : "r"(addr));
}
__device__ __forceinline__ void mma16816(float* c, const uint32_t* a,
                                         uint32_t b0, uint32_t b1) {
    asm volatile("mma.sync.aligned.m16n8k16.row.col.f32.bf16.bf16.f32 "
                 "{%0,%1,%2,%3}, {%4,%5,%6,%7}, {%8,%9}, {%0,%1,%2,%3};"
                 : "+f"(c[0]), "+f"(c[1]), "+f"(c[2]), "+f"(c[3])
                 : "r"(a[0]), "r"(a[1]), "r"(a[2]), "r"(a[3]), "r"(b0), "r"(b1));
}

// ---------------------------------------------------------------------------
// Raw-mma bf16 GEMM, 3-stage cp.async ring, register DB frags, interleaved
// LDSM/mma issue. C[M,N] = A[M,K] @ B[K,N] (+bias). Block 128x128, chunk 64.
// ---------------------------------------------------------------------------
#define ALD_A 72
#define ALD_B 136
#define STG_A (128*ALD_A*2)              // 18432
#define STG_BYTES (STG_A + 64*ALD_B*2)   // 35840
#define GEMM_SMEM (3*STG_BYTES)          // 107520
#define CLD 132

template<bool BF16_OUT>
__global__ __launch_bounds__(256, 2)
void gemm_mma(const __nv_bfloat16* __restrict__ A, const __nv_bfloat16* __restrict__ B,
              const float* __restrict__ bias, void* __restrict__ Cout,
              int M, int N, int K)
{
    extern __shared__ char sh[];
    const uint32_t sb = smem_u32(sh);
    const int tid = threadIdx.x;
    const int w = tid >> 5, lane = tid & 31;
    const int wm = w >> 1, wn = w & 1;
    const int lmat = lane >> 3, lrr = lane & 7;
    const int row0 = blockIdx.y * 128;
    const int col0 = blockIdx.x * 128;

    float acc[2][8][4];
#pragma unroll
    for (int i = 0; i < 2; i++)
#pragma unroll
        for (int nt = 0; nt < 8; nt++)
#pragma unroll
            for (int j = 0; j < 4; j++) acc[i][nt][j] = 0.f;

    const int nchunk = K / 64;

    auto issue = [&](int c, int s) {
        const uint32_t aB = sb + s * STG_BYTES;
        const uint32_t bB = aB + STG_A;
        const __nv_bfloat16* Ag = A + (size_t)row0 * K + c * 64;
        const __nv_bfloat16* Bg = B + (size_t)(c * 64) * N + col0;
#pragma unroll
        for (int i = 0; i < 4; i++) {
            const int u = tid + i * 256;
            const int r = u >> 3, cc = u & 7;
            cp_async16(aB + r * (ALD_A * 2) + cc * 16, Ag + (size_t)r * K + cc * 8);
        }
#pragma unroll
        for (int i = 0; i < 4; i++) {
            const int u = tid + i * 256;
            const int r = u >> 4, cc = u & 15;
            cp_async16(bB + r * (ALD_B * 2) + cc * 16, Bg + (size_t)r * N + cc * 8);
        }
        CP_COMMIT();
    };

    const uint32_t a_base = (uint32_t)(wm * 32 + (lmat & 1) * 8 + lrr) * (ALD_A * 2)
                          + (lmat >> 1) * 16;
    const uint32_t b_base = (uint32_t)((lmat & 1) * 8 + lrr) * (ALD_B * 2)
                          + wn * 128 + (lmat >> 1) * 16;

    uint32_t af[2][2][4];
    uint32_t bfr[2][4][4];

    issue(0, 0);
    issue(1, 1);
    for (int c = 0; c < nchunk; c++) {
        const int s = c % 3;
        CP_WAIT(1);
        __syncthreads();
        const uint32_t aS = sb + s * STG_BYTES;
        const uint32_t bS = aS + STG_A;

        // preload ks=0 fragments
        {
            const uint32_t aadr = aS + a_base;
            ldmx4(af[0][0], aadr);
            ldmx4(af[0][1], aadr + 16 * (ALD_A * 2));
            const uint32_t badr = bS + b_base;
#pragma unroll
            for (int p = 0; p < 4; p++) ldmx4t(bfr[0][p], badr + p * 32);
        }
#pragma unroll
        for (int ks = 0; ks < 4; ks++) {
            const int cur = ks & 1;
            const int nxt = cur ^ 1;
            const uint32_t aadr = aS + a_base + (ks + 1) * 32;
            const uint32_t badr = bS + b_base + (uint32_t)((ks + 1) * 16) * (ALD_B * 2);
#pragma unroll
            for (int p = 0; p < 4; p++) {
                mma16816(acc[0][2 * p],     af[cur][0], bfr[cur][p][0], bfr[cur][p][1]);
                mma16816(acc[0][2 * p + 1], af[cur][0], bfr[cur][p][2], bfr[cur][p][3]);
                mma16816(acc[1][2 * p],     af[cur][1], bfr[cur][p][0], bfr[cur][p][1]);
                mma16816(acc[1][2 * p + 1], af[cur][1], bfr[cur][p][2], bfr[cur][p][3]);
                if (ks < 3) {   // spread next-ks LDSMs between mma quads
                    if (p == 0)      ldmx4(af[nxt][0], aadr);
                    else if (p == 1) ldmx4(af[nxt][1], aadr + 16 * (ALD_A * 2));
                    else if (p == 2) { ldmx4t(bfr[nxt][0], badr);
                                       ldmx4t(bfr[nxt][1], badr + 32); }
                    else             { ldmx4t(bfr[nxt][2], badr + 64);
                                       ldmx4t(bfr[nxt][3], badr + 96); }
                }
            }
        }
        if (c + 2 < nchunk) issue(c + 2, (c + 2) % 3);
        else                CP_COMMIT();
    }
    __syncthreads();

    // Stage fp32 result in smem
    {
        float* Cs = (float*)sh;
        const int r = wm * 32 + (lane >> 2);
        const int cb = wn * 64 + (lane & 3) * 2;
#pragma unroll
        for (int i = 0; i < 2; i++)
#pragma unroll
            for (int nt = 0; nt < 8; nt++) {
                *(float2*)&Cs[(r + i * 16) * CLD + cb + nt * 8] =
                    make_float2(acc[i][nt][0], acc[i][nt][1]);
                *(float2*)&Cs[(r + i * 16 + 8) * CLD + cb + nt * 8] =
                    make_float2(acc[i][nt][2], acc[i][nt][3]);
            }
    }
    __syncthreads();

    const float* Cs = (const float*)sh;
    if (BF16_OUT) {
        __nv_bfloat16* C = (__nv_bfloat16*)Cout;
#pragma unroll
        for (int i = 0; i < 8; i++) {
            const int u = tid + i * 256;
            const int r = u >> 4, cg = (u & 15) * 8;
            const float4 bv0 = *(const float4*)(bias + col0 + cg);
            const float4 bv1 = *(const float4*)(bias + col0 + cg + 4);
            const float4 v0 = *(const float4*)(Cs + r * CLD + cg);
            const float4 v1 = *(const float4*)(Cs + r * CLD + cg + 4);
            __nv_bfloat162 p0 = __floats2bfloat162_rn(v0.x + bv0.x, v0.y + bv0.y);
            __nv_bfloat162 p1 = __floats2bfloat162_rn(v0.z + bv0.z, v0.w + bv0.w);
            __nv_bfloat162 p2 = __floats2bfloat162_rn(v1.x + bv1.x, v1.y + bv1.y);
            __nv_bfloat162 p3 = __floats2bfloat162_rn(v1.z + bv1.z, v1.w + bv1.w);
            uint4 o;
            o.x = *(uint32_t*)&p0; o.y = *(uint32_t*)&p1;
            o.z = *(uint32_t*)&p2; o.w = *(uint32_t*)&p3;
            *(uint4*)(C + (size_t)(row0 + r) * N + col0 + cg) = o;
        }
    } else {
        float* C = (float*)Cout;
#pragma unroll
        for (int i = 0; i < 16; i++) {
            const int u = tid + i * 256;
            const int r = u >> 5, cg = (u & 31) * 4;
            const float4 v = *(const float4*)(Cs + r * CLD + cg);
            *(float4*)(C + (size_t)(row0 + r) * N + col0 + cg) = v;
        }
    }
}

// ---------------------------------------------------------------------------
// Prep: fp32 -> bf16 convert
// ---------------------------------------------------------------------------
__global__ __launch_bounds__(256)
void cvt_bf16_kernel(const float* __restrict__ X, __nv_bfloat16* __restrict__ Y)
{
    const int i = (blockIdx.x * 256 + threadIdx.x) * 4;
    const float4 v = *(const float4*)(X + i);
    __nv_bfloat162 a = __floats2bfloat162_rn(v.x, v.y);
    __nv_bfloat162 b = __floats2bfloat162_rn(v.z, v.w);
    uint2 o; o.x = *(uint32_t*)&a; o.y = *(uint32_t*)&b;
    *(uint2*)(Y + i) = o;
}

// ---------------------------------------------------------------------------
// FA2 flash attention, mma.sync bf16, ring-4 cp.async, interleaved frags,
// thread-local l (deferred quad reduction).
// ---------------------------------------------------------------------------
#define KLD 144
#define AT_Q  0
#define AT_KV (128*KLD)
#define AT_STG (64*KLD*2)
#define AT_SMEM (AT_KV + 4*AT_STG)   // 92160

__global__ __launch_bounds__(256, 2)
void attn_mma(const __nv_bfloat16* __restrict__ qkv, __nv_bfloat16* __restrict__ out)
{
    extern __shared__ char sh[];
    const uint32_t sb = smem_u32(sh);
    const int tid = threadIdx.x;
    const int warp = tid >> 5, lane = tid & 31;
    const int q0 = blockIdx.x * 128;
    const int bh = blockIdx.y, b = bh >> 4, h = bh & 15;
    const __nv_bfloat16* base = qkv + (size_t)(b * TT) * D3 + h * DKK;

    {
        const __nv_bfloat162 sc = __float2bfloat162_rn(0.125f);
#pragma unroll
        for (int i = 0; i < 4; i++) {
            const int u = tid + i * 256;
            const int r = u >> 3, cg = (u & 7) * 8;
            uint4 raw = *(const uint4*)(base + (size_t)(q0 + r) * D3 + cg);
            __nv_bfloat162* pp = (__nv_bfloat162*)&raw;
            pp[0] = __hmul2(pp[0], sc); pp[1] = __hmul2(pp[1], sc);
            pp[2] = __hmul2(pp[2], sc); pp[3] = __hmul2(pp[3], sc);
            *(uint4*)(sh + AT_Q + r * KLD + cg * 2) = raw;
        }
    }

    auto issue = [&](int kt, int s) {
        const uint32_t kb = sb + AT_KV + s * AT_STG;
        const uint32_t vb = kb + 64 * KLD;
        const __nv_bfloat16* Kg = base + DD + (size_t)(kt * 64) * D3;
        const __nv_bfloat16* Vg = base + 2 * DD + (size_t)(kt * 64) * D3;
#pragma unroll
        for (int i = 0; i < 2; i++) {
            const int u = tid + i * 256;
            const int r = u >> 3, cc = u & 7;
            cp_async16(kb + r * KLD + cc * 16, Kg + (size_t)r * D3 + cc * 8);
        }
#pragma unroll
        for (int i = 0; i < 2; i++) {
            const int u = tid + i * 256;
            const int r = u >> 3, cc = u & 7;
            cp_async16(vb + r * KLD + cc * 16, Vg + (size_t)r * D3 + cc * 8);
        }
        CP_COMMIT();
    };

    issue(0, 0);
    issue(1, 1);
    issue(2, 2);
    __syncthreads();

    const int lmat = lane >> 3, lrr = lane & 7;

    uint32_t qa[4][4];
    {
        const uint32_t qoff = sb + AT_Q +
            (uint32_t)(warp * 16 + (lmat & 1) * 8 + lrr) * KLD + (lmat >> 1) * 16;
#pragma unroll
        for (int kk = 0; kk < 4; kk++) ldmx4(qa[kk], qoff + kk * 32);
    }

    const uint32_t koff = (uint32_t)((lmat >> 1) * 8 + lrr) * KLD + (lmat & 1) * 16;
    const uint32_t voff = (uint32_t)((lmat & 1) * 8 + lrr) * KLD + (lmat >> 1) * 16;

    float oacc[8][4];
#pragma unroll
    for (int nt = 0; nt < 8; nt++)
#pragma unroll
        for (int j = 0; j < 4; j++) oacc[nt][j] = 0.f;
    float m0 = -1e30f, m1 = -1e30f, l0 = 0.f, l1 = 0.f;   // l thread-local now

    for (int kt = 0; kt < TT / 64; kt++) {
        const int s = kt & 3;
        CP_WAIT(2);
        __syncthreads();

        const uint32_t kb = sb + AT_KV + s * AT_STG;
        const uint32_t vb = kb + 64 * KLD;

        // S = Q @ K^T, K-frag DB, interleaved LDSM/mma
        float sacc[8][4];
#pragma unroll
        for (int nt = 0; nt < 8; nt++)
#pragma unroll
            for (int j = 0; j < 4; j++) sacc[nt][j] = 0.f;

        uint32_t kf[2][4][4];
#pragma unroll
        for (int p = 0; p < 4; p++)
            ldmx4(kf[0][p], kb + (uint32_t)(p * 16) * KLD + koff);
#pragma unroll
        for (int kk = 0; kk < 4; kk++) {
            const int cur = kk & 1;
#pragma unroll
            for (int p = 0; p < 4; p++) {
                mma16816(sacc[2 * p],     qa[kk], kf[cur][p][0], kf[cur][p][1]);
                mma16816(sacc[2 * p + 1], qa[kk], kf[cur][p][2], kf[cur][p][3]);
                if (kk < 3)
                    ldmx4(kf[cur ^ 1][p],
                          kb + (uint32_t)(p * 16) * KLD + (kk + 1) * 32 + koff);
            }
        }

        // Online softmax (max shuffles only; sum stays thread-local)
        float mx0 = -1e30f, mx1 = -1e30f;
#pragma unroll
        for (int nt = 0; nt < 8; nt++) {
            mx0 = fmaxf(mx0, fmaxf(sacc[nt][0], sacc[nt][1]));
            mx1 = fmaxf(mx1, fmaxf(sacc[nt][2], sacc[nt][3]));
        }
        mx0 = fmaxf(mx0, __shfl_xor_sync(0xffffffffu, mx0, 1));
        mx0 = fmaxf(mx0, __shfl_xor_sync(0xffffffffu, mx0, 2));
        mx1 = fmaxf(mx1, __shfl_xor_sync(0xffffffffu, mx1, 1));
        mx1 = fmaxf(mx1, __shfl_xor_sync(0xffffffffu, mx1, 2));
        const float mn0 = fmaxf(m0, mx0), mn1 = fmaxf(m1, mx1);
        const float al0 = __expf(m0 - mn0), al1 = __expf(m1 - mn1);
        float s0 = 0.f, s1 = 0.f;
#pragma unroll
        for (int nt = 0; nt < 8; nt++) {
            sacc[nt][0] = __expf(sacc[nt][0] - mn0); s0 += sacc[nt][0];
            sacc[nt][1] = __expf(sacc[nt][1] - mn0); s0 += sacc[nt][1];
            sacc[nt][2] = __expf(sacc[nt][2] - mn1); s1 += sacc[nt][2];
            sacc[nt][3] = __expf(sacc[nt][3] - mn1); s1 += sacc[nt][3];
        }
        l0 = l0 * al0 + s0; l1 = l1 * al1 + s1;
        m0 = mn0; m1 = mn1;
#pragma unroll
        for (int nt = 0; nt < 8; nt++) {
            oacc[nt][0] *= al0; oacc[nt][1] *= al0;
            oacc[nt][2] *= al1; oacc[nt][3] *= al1;
        }

        // O += P @ V, V-frag DB, interleaved LDSM/mma
        uint32_t vf[2][4][4];
#pragma unroll
        for (int p = 0; p < 4; p++)
            ldmx4t(vf[0][p], vb + p * 32 + voff);
#pragma unroll
        for (int kk = 0; kk < 4; kk++) {
            const int cur = kk & 1;
            uint32_t pa[4];
            pa[0] = bf2pack(sacc[2 * kk][0],     sacc[2 * kk][1]);
            pa[1] = bf2pack(sacc[2 * kk][2],     sacc[2 * kk][3]);
            pa[2] = bf2pack(sacc[2 * kk + 1][0], sacc[2 * kk + 1][1]);
            pa[3] = bf2pack(sacc[2 * kk + 1][2], sacc[2 * kk + 1][3]);
#pragma unroll
            for (int p = 0; p < 4; p++) {
                mma16816(oacc[2 * p],     pa, vf[cur][p][0], vf[cur][p][1]);
                mma16816(oacc[2 * p + 1], pa, vf[cur][p][2], vf[cur][p][3]);
                if (kk < 3)
                    ldmx4t(vf[cur ^ 1][p],
                           vb + (uint32_t)((kk + 1) * 16) * KLD + p * 32 + voff);
            }
        }
        if (kt + 3 < TT / 64) issue(kt + 3, (kt + 3) & 3);
        else                  CP_COMMIT();
    }

    // Final l: quad-reduce thread-local partials
    l0 += __shfl_xor_sync(0xffffffffu, l0, 1);
    l0 += __shfl_xor_sync(0xffffffffu, l0, 2);
    l1 += __shfl_xor_sync(0xffffffffu, l1, 1);
    l1 += __shfl_xor_sync(0xffffffffu, l1, 2);

    // Epilogue: O / l -> bf16
    {
        const float i0 = 1.f / l0, i1 = 1.f / l1;
        const size_t r0 = (size_t)(b * TT + q0 + warp * 16 + (lane >> 2)) * DD
                        + h * DKK + (lane & 3) * 2;
        const size_t r1 = r0 + 8 * DD;
#pragma unroll
        for (int nt = 0; nt < 8; nt++) {
            *(uint32_t*)(out + r0 + nt * 8) = bf2pack(oacc[nt][0] * i0, oacc[nt][1] * i0);
            *(uint32_t*)(out + r1 + nt * 8) = bf2pack(oacc[nt][2] * i1, oacc[nt][3] * i1);
        }
    }
}

// ---------------------------------------------------------------------------
// Fused: res = x + C_raw + b_out ; LayerNorm
// ---------------------------------------------------------------------------
__global__ __launch_bounds__(256)
void ln_fused(const float* __restrict__ Craw, const float* __restrict__ x,
              const float* __restrict__ bout, const float* __restrict__ gamma,
              const float* __restrict__ beta, float* __restrict__ Y)
{
    __shared__ float red[8];
    const int row = blockIdx.x;
    const int tid = threadIdx.x;
    const int c = tid * 4;
    const float4 cv = *(const float4*)(Craw + (size_t)row * DD + c);
    const float4 xv = *(const float4*)(x + (size_t)row * DD + c);
    const float4 bv = *(const float4*)(bout + c);
    float4 v;
    v.x = cv.x + xv.x + bv.x;
    v.y = cv.y + xv.y + bv.y;
    v.z = cv.z + xv.z + bv.z;
    v.w = cv.w + xv.w + bv.w;

    float s = v.x + v.y + v.z + v.w;
#pragma unroll
    for (int off = 16; off >= 1; off >>= 1)
        s += __shfl_xor_sync(0xffffffffu, s, off);
    if ((tid & 31) == 0) red[tid >> 5] = s;
    __syncthreads();
    float tot = red[0] + red[1] + red[2] + red[3] + red[4] + red[5] + red[6] + red[7];
    const float mean = tot * (1.f / 1024.f);
    __syncthreads();

    const float dx = v.x - mean, dy = v.y - mean, dz = v.z - mean, dw = v.w - mean;
    float ss = dx * dx + dy * dy + dz * dz + dw * dw;
#pragma unroll
    for (int off = 16; off >= 1; off >>= 1)
        ss += __shfl_xor_sync(0xffffffffu, ss, off);
    if ((tid & 31) == 0) red[tid >> 5] = ss;
    __syncthreads();
    float var = (red[0] + red[1] + red[2] + red[3] + red[4] + red[5] + red[6] + red[7])
                * (1.f / 1024.f);
    const float rstd = rsqrtf(var + 1e-5f);

    const float4 g = *(const float4*)(gamma + c);
    const float4 be = *(const float4*)(beta + c);
    float4 o;
    o.x = dx * rstd * g.x + be.x;
    o.y = dy * rstd * g.y + be.y;
    o.z = dz * rstd * g.z + be.z;
    o.w = dw * rstd * g.w + be.w;
    *(float4*)(Y + (size_t)row * DD + c) = o;
}

// ---------------------------------------------------------------------------
extern "C" void kernel_launch(void* const* d_in, const int* in_sizes, int n_in,
                              void* d_out, int out_size)
{
    const float* x     = (const float*)d_in[0];
    const float* Wqkv  = (const float*)d_in[1];
    const float* bqkv  = (const float*)d_in[2];
    const float* Wout  = (const float*)d_in[3];
    const float* bout  = (const float*)d_in[4];
    const float* gamma = (const float*)d_in[5];
    const float* beta  = (const float*)d_in[6];
    float* out = (float*)d_out;

    __nv_bfloat16 *xb, *wqkv, *wout, *qkv, *att;
    float* res;
    cudaGetSymbolAddress((void**)&xb, g_xb);
    cudaGetSymbolAddress((void**)&wqkv, g_wqkv);
    cudaGetSymbolAddress((void**)&wout, g_wout);
    cudaGetSymbolAddress((void**)&qkv, g_qkv);
    cudaGetSymbolAddress((void**)&att, g_att);
    cudaGetSymbolAddress((void**)&res, g_res);

    cudaFuncSetAttribute(attn_mma, cudaFuncAttributeMaxDynamicSharedMemorySize, AT_SMEM);
    cudaFuncSetAttribute(gemm_mma<true>, cudaFuncAttributeMaxDynamicSharedMemorySize, GEMM_SMEM);
    cudaFuncSetAttribute(gemm_mma<false>, cudaFuncAttributeMaxDynamicSharedMemorySize, GEMM_SMEM);

    // 0. Prep: convert inputs to bf16
    cvt_bf16_kernel<<<NTOK * DD / 1024, 256>>>(x, xb);
    cvt_bf16_kernel<<<DD * D3 / 1024, 256>>>(Wqkv, wqkv);
    cvt_bf16_kernel<<<DD * DD / 1024, 256>>>(Wout, wout);

    // 1. QKV projection + bias (bf16 out)
    {
        dim3 grid(D3 / 128, NTOK / 128);
        gemm_mma<true><<<grid, 256, GEMM_SMEM>>>(xb, wqkv, bqkv, qkv, NTOK, D3, DD);
    }
    // 2. Attention (register-resident FA2, ring-4, interleaved frags)
    {
        dim3 grid(TT / 128, BB * HH);
        attn_mma<<<grid, 256, AT_SMEM>>>(qkv, att);
    }
    // 3. Output projection (fp32 out; bias+residual fused into LN)
    {
        dim3 grid(DD / 128, NTOK / 128);
        gemm_mma<false><<<grid, 256, GEMM_SMEM>>>(att, wout, nullptr, res, NTOK, DD, DD);
    }
    // 4. res = x + C + b_out, then LayerNorm
    ln_fused<<<NTOK, 256>>>(res, x, bout, gamma, beta, out);
}

// round 13
// speedup vs baseline: 15.0667x; 1.0437x over previous
#include <cuda_runtime.h>
#include <cuda_bf16.h>
#include <math.h>
#include <cstdint>

#define BB 4
#define TT 2048
#define DD 1024
#define HH 16
#define DKK 64
#define NTOK (BB*TT)      // 8192
#define D3 (3*DD)         // 3072

// Scratch (allocation-free rule: __device__ globals)
__device__ __nv_bfloat16 g_xb[NTOK * DD];
__device__ __nv_bfloat16 g_wqkv[DD * D3];
__device__ __nv_bfloat16 g_wout[DD * DD];
__device__ __nv_bfloat16 g_qkv[NTOK * D3];     // QKV bf16 WITH bias
__device__ __nv_bfloat16 g_att[NTOK * DD];
__device__ float         g_res[NTOK * DD];

__device__ __forceinline__ uint32_t smem_u32(const void* p) {
    uint32_t a;
    asm("{ .reg .u64 t; cvta.to.shared.u64 t, %1; cvt.u32.u64 %0, t; }" : "=r"(a) : "l"(p));
    return a;
}
__device__ __forceinline__ void cp_async16(uint32_t s, const void* g) {
    asm volatile("cp.async.cg.shared.global [%0], [%1], 16;" :: "r"(s), "l"(g) : "memory");
}
#define CP_COMMIT() asm volatile("cp.async.commit_group;" ::: "memory")
#define CP_WAIT(N)  asm volatile("cp.async.wait_group %0;" :: "n"(N) : "memory")

__device__ __forceinline__ uint32_t bf2pack(float x, float y) {
    __nv_bfloat162 p = __floats2bfloat162_rn(x, y);
    return *(uint32_t*)&p;
}
__device__ __forceinline__ void ldmx4(uint32_t* r, uint32_t addr) {
    asm volatile("ldmatrix.sync.aligned.m8n8.x4.shared.b16 {%0,%1,%2,%3}, [%4];"
                 : "=r"(r[0]), "=r"(r[1]), "=r"(r[2]), "=r"(r[3]) : "r"(addr));
}
__device__ __forceinline__ void ldmx4t(uint32_t* r, uint32_t addr) {
    asm volatile("ldmatrix.sync.aligned.m8n8.x4.trans.shared.b16 {%0,%1,%2,%3}, [%4];"
                 : "=r"(r[0]), "=r"(r[1]), "=r"(r[2]), "=r"(r[3]) : "r"(addr));
}
__device__ __forceinline__ void mma16816(float* c, const uint32_t* a,
                                         uint32_t b0, uint32_t b1) {
    asm volatile("mma.sync.aligned.m16n8k16.row.col.f32.bf16.bf16.f32 "
                 "{%0,%1,%2,%3}, {%4,%5,%6,%7}, {%8,%9}, {%0,%1,%2,%3};"
                 : "+f"(c[0]), "+f"(c[1]), "+f"(c[2]), "+f"(c[3])
                 : "r"(a[0]), "r"(a[1]), "r"(a[2]), "r"(a[3]), "r"(b0), "r"(b1));
}

// ---------------------------------------------------------------------------
// Raw-mma bf16 GEMM (unchanged from R11): 3-stage ring, register DB frags.
// ---------------------------------------------------------------------------
#define ALD_A 72
#define ALD_B 136
#define STG_A (128*ALD_A*2)
#define STG_BYTES (STG_A + 64*ALD_B*2)   // 35840
#define GEMM_SMEM (3*STG_BYTES)          // 107520
#define CLD 132

template<bool BF16_OUT>
__global__ __launch_bounds__(256, 2)
void gemm_mma(const __nv_bfloat16* __restrict__ A, const __nv_bfloat16* __restrict__ B,
              const float* __restrict__ bias, void* __restrict__ Cout,
              int M, int N, int K)
{
    extern __shared__ char sh[];
    const uint32_t sb = smem_u32(sh);
    const int tid = threadIdx.x;
    const int w = tid >> 5, lane = tid & 31;
    const int wm = w >> 1, wn = w & 1;
    const int lmat = lane >> 3, lrr = lane & 7;
    const int row0 = blockIdx.y * 128;
    const int col0 = blockIdx.x * 128;

    float acc[2][8][4];
#pragma unroll
    for (int i = 0; i < 2; i++)
#pragma unroll
        for (int nt = 0; nt < 8; nt++)
#pragma unroll
            for (int j = 0; j < 4; j++) acc[i][nt][j] = 0.f;

    const int nchunk = K / 64;

    auto issue = [&](int c, int s) {
        const uint32_t aB = sb + s * STG_BYTES;
        const uint32_t bB = aB + STG_A;
        const __nv_bfloat16* Ag = A + (size_t)row0 * K + c * 64;
        const __nv_bfloat16* Bg = B + (size_t)(c * 64) * N + col0;
#pragma unroll
        for (int i = 0; i < 4; i++) {
            const int u = tid + i * 256;
            const int r = u >> 3, cc = u & 7;
            cp_async16(aB + r * (ALD_A * 2) + cc * 16, Ag + (size_t)r * K + cc * 8);
        }
#pragma unroll
        for (int i = 0; i < 4; i++) {
            const int u = tid + i * 256;
            const int r = u >> 4, cc = u & 15;
            cp_async16(bB + r * (ALD_B * 2) + cc * 16, Bg + (size_t)r * N + cc * 8);
        }
        CP_COMMIT();
    };

    const uint32_t a_base = (uint32_t)(wm * 32 + (lmat & 1) * 8 + lrr) * (ALD_A * 2)
                          + (lmat >> 1) * 16;
    const uint32_t b_base = (uint32_t)((lmat & 1) * 8 + lrr) * (ALD_B * 2)
                          + wn * 128 + (lmat >> 1) * 16;

    uint32_t af[2][2][4];
    uint32_t bfr[2][4][4];

    issue(0, 0);
    issue(1, 1);
    for (int c = 0; c < nchunk; c++) {
        const int s = c % 3;
        CP_WAIT(1);
        __syncthreads();
        const uint32_t aS = sb + s * STG_BYTES;
        const uint32_t bS = aS + STG_A;

        {
            const uint32_t aadr = aS + a_base;
            ldmx4(af[0][0], aadr);
            ldmx4(af[0][1], aadr + 16 * (ALD_A * 2));
            const uint32_t badr = bS + b_base;
#pragma unroll
            for (int p = 0; p < 4; p++) ldmx4t(bfr[0][p], badr + p * 32);
        }
#pragma unroll
        for (int ks = 0; ks < 4; ks++) {
            const int cur = ks & 1;
            const int nxt = cur ^ 1;
            const uint32_t aadr = aS + a_base + (ks + 1) * 32;
            const uint32_t badr = bS + b_base + (uint32_t)((ks + 1) * 16) * (ALD_B * 2);
#pragma unroll
            for (int p = 0; p < 4; p++) {
                mma16816(acc[0][2 * p],     af[cur][0], bfr[cur][p][0], bfr[cur][p][1]);
                mma16816(acc[0][2 * p + 1], af[cur][0], bfr[cur][p][2], bfr[cur][p][3]);
                mma16816(acc[1][2 * p],     af[cur][1], bfr[cur][p][0], bfr[cur][p][1]);
                mma16816(acc[1][2 * p + 1], af[cur][1], bfr[cur][p][2], bfr[cur][p][3]);
                if (ks < 3) {
                    if (p == 0)      ldmx4(af[nxt][0], aadr);
                    else if (p == 1) ldmx4(af[nxt][1], aadr + 16 * (ALD_A * 2));
                    else if (p == 2) { ldmx4t(bfr[nxt][0], badr);
                                       ldmx4t(bfr[nxt][1], badr + 32); }
                    else             { ldmx4t(bfr[nxt][2], badr + 64);
                                       ldmx4t(bfr[nxt][3], badr + 96); }
                }
            }
        }
        if (c + 2 < nchunk) issue(c + 2, (c + 2) % 3);
        else                CP_COMMIT();
    }
    __syncthreads();

    {
        float* Cs = (float*)sh;
        const int r = wm * 32 + (lane >> 2);
        const int cb = wn * 64 + (lane & 3) * 2;
#pragma unroll
        for (int i = 0; i < 2; i++)
#pragma unroll
            for (int nt = 0; nt < 8; nt++) {
                *(float2*)&Cs[(r + i * 16) * CLD + cb + nt * 8] =
                    make_float2(acc[i][nt][0], acc[i][nt][1]);
                *(float2*)&Cs[(r + i * 16 + 8) * CLD + cb + nt * 8] =
                    make_float2(acc[i][nt][2], acc[i][nt][3]);
            }
    }
    __syncthreads();

    const float* Cs = (const float*)sh;
    if (BF16_OUT) {
        __nv_bfloat16* C = (__nv_bfloat16*)Cout;
#pragma unroll
        for (int i = 0; i < 8; i++) {
            const int u = tid + i * 256;
            const int r = u >> 4, cg = (u & 15) * 8;
            const float4 bv0 = *(const float4*)(bias + col0 + cg);
            const float4 bv1 = *(const float4*)(bias + col0 + cg + 4);
            const float4 v0 = *(const float4*)(Cs + r * CLD + cg);
            const float4 v1 = *(const float4*)(Cs + r * CLD + cg + 4);
            __nv_bfloat162 p0 = __floats2bfloat162_rn(v0.x + bv0.x, v0.y + bv0.y);
            __nv_bfloat162 p1 = __floats2bfloat162_rn(v0.z + bv0.z, v0.w + bv0.w);
            __nv_bfloat162 p2 = __floats2bfloat162_rn(v1.x + bv1.x, v1.y + bv1.y);
            __nv_bfloat162 p3 = __floats2bfloat162_rn(v1.z + bv1.z, v1.w + bv1.w);
            uint4 o;
            o.x = *(uint32_t*)&p0; o.y = *(uint32_t*)&p1;
            o.z = *(uint32_t*)&p2; o.w = *(uint32_t*)&p3;
            *(uint4*)(C + (size_t)(row0 + r) * N + col0 + cg) = o;
        }
    } else {
        float* C = (float*)Cout;
#pragma unroll
        for (int i = 0; i < 16; i++) {
            const int u = tid + i * 256;
            const int r = u >> 5, cg = (u & 31) * 4;
            const float4 v = *(const float4*)(Cs + r * CLD + cg);
            *(float4*)(C + (size_t)(row0 + r) * N + col0 + cg) = v;
        }
    }
}

// ---------------------------------------------------------------------------
// Prep: fp32 -> bf16 convert
// ---------------------------------------------------------------------------
__global__ __launch_bounds__(256)
void cvt_bf16_kernel(const float* __restrict__ X, __nv_bfloat16* __restrict__ Y)
{
    const int i = (blockIdx.x * 256 + threadIdx.x) * 4;
    const float4 v = *(const float4*)(X + i);
    __nv_bfloat162 a = __floats2bfloat162_rn(v.x, v.y);
    __nv_bfloat162 b = __floats2bfloat162_rn(v.z, v.w);
    uint2 o; o.x = *(uint32_t*)&a; o.y = *(uint32_t*)&b;
    *(uint2*)(Y + i) = o;
}

// ---------------------------------------------------------------------------
// FA2 flash attention: 4 warps x 32 queries/warp (q-tile 128), mma.sync bf16,
// ring-4 cp.async. Halved K/V fragment redundancy vs 8-warp version.
// ---------------------------------------------------------------------------
#define KLD 144
#define AT_Q  0
#define AT_KV (128*KLD)
#define AT_STG (64*KLD*2)
#define AT_SMEM (AT_KV + 4*AT_STG)   // 92160

__global__ __launch_bounds__(128, 2)
void attn_mma(const __nv_bfloat16* __restrict__ qkv, __nv_bfloat16* __restrict__ out)
{
    extern __shared__ char sh[];
    const uint32_t sb = smem_u32(sh);
    const int tid = threadIdx.x;
    const int warp = tid >> 5, lane = tid & 31;
    const int q0 = blockIdx.x * 128;
    const int bh = blockIdx.y, b = bh >> 4, h = bh & 15;
    const __nv_bfloat16* base = qkv + (size_t)(b * TT) * D3 + h * DKK;

    // Fill Q smem (scaled by 1/8)
    {
        const __nv_bfloat162 sc = __float2bfloat162_rn(0.125f);
#pragma unroll
        for (int i = 0; i < 8; i++) {
            const int u = tid + i * 128;          // 1024 units of 8 bf16
            const int r = u >> 3, cg = (u & 7) * 8;
            uint4 raw = *(const uint4*)(base + (size_t)(q0 + r) * D3 + cg);
            __nv_bfloat162* pp = (__nv_bfloat162*)&raw;
            pp[0] = __hmul2(pp[0], sc); pp[1] = __hmul2(pp[1], sc);
            pp[2] = __hmul2(pp[2], sc); pp[3] = __hmul2(pp[3], sc);
            *(uint4*)(sh + AT_Q + r * KLD + cg * 2) = raw;
        }
    }

    auto issue = [&](int kt, int s) {
        const uint32_t kb = sb + AT_KV + s * AT_STG;
        const uint32_t vb = kb + 64 * KLD;
        const __nv_bfloat16* Kg = base + DD + (size_t)(kt * 64) * D3;
        const __nv_bfloat16* Vg = base + 2 * DD + (size_t)(kt * 64) * D3;
#pragma unroll
        for (int i = 0; i < 4; i++) {
            const int u = tid + i * 128;
            const int r = u >> 3, cc = u & 7;
            cp_async16(kb + r * KLD + cc * 16, Kg + (size_t)r * D3 + cc * 8);
        }
#pragma unroll
        for (int i = 0; i < 4; i++) {
            const int u = tid + i * 128;
            const int r = u >> 3, cc = u & 7;
            cp_async16(vb + r * KLD + cc * 16, Vg + (size_t)r * D3 + cc * 8);
        }
        CP_COMMIT();
    };

    issue(0, 0);
    issue(1, 1);
    issue(2, 2);
    __syncthreads();

    const int lmat = lane >> 3, lrr = lane & 7;

    // Q fragments: 2 m-tiles (warp*32 + mi*16), 4 k-steps
    uint32_t qa[2][4][4];
    {
        const uint32_t qoff = sb + AT_Q +
            (uint32_t)(warp * 32 + (lmat & 1) * 8 + lrr) * KLD + (lmat >> 1) * 16;
#pragma unroll
        for (int mi = 0; mi < 2; mi++)
#pragma unroll
            for (int kk = 0; kk < 4; kk++)
                ldmx4(qa[mi][kk], qoff + mi * 16 * KLD + kk * 32);
    }

    const uint32_t koff = (uint32_t)((lmat >> 1) * 8 + lrr) * KLD + (lmat & 1) * 16;
    const uint32_t voff = (uint32_t)((lmat & 1) * 8 + lrr) * KLD + (lmat >> 1) * 16;

    float oacc[2][8][4];
#pragma unroll
    for (int mi = 0; mi < 2; mi++)
#pragma unroll
        for (int nt = 0; nt < 8; nt++)
#pragma unroll
            for (int j = 0; j < 4; j++) oacc[mi][nt][j] = 0.f;
    float mrow[2][2], lrow[2][2];
#pragma unroll
    for (int mi = 0; mi < 2; mi++) {
        mrow[mi][0] = -1e30f; mrow[mi][1] = -1e30f;
        lrow[mi][0] = 0.f;    lrow[mi][1] = 0.f;
    }

    for (int kt = 0; kt < TT / 64; kt++) {
        const int s = kt & 3;
        CP_WAIT(2);
        __syncthreads();

        const uint32_t kb = sb + AT_KV + s * AT_STG;
        const uint32_t vb = kb + 64 * KLD;

        // S = Q @ K^T (2 m-tiles share each K fragment)
        float sacc[2][8][4];
#pragma unroll
        for (int mi = 0; mi < 2; mi++)
#pragma unroll
            for (int nt = 0; nt < 8; nt++)
#pragma unroll
                for (int j = 0; j < 4; j++) sacc[mi][nt][j] = 0.f;

        uint32_t kf[2][4][4];
#pragma unroll
        for (int p = 0; p < 4; p++)
            ldmx4(kf[0][p], kb + (uint32_t)(p * 16) * KLD + koff);
#pragma unroll
        for (int kk = 0; kk < 4; kk++) {
            const int cur = kk & 1;
#pragma unroll
            for (int p = 0; p < 4; p++) {
                mma16816(sacc[0][2 * p],     qa[0][kk], kf[cur][p][0], kf[cur][p][1]);
                mma16816(sacc[0][2 * p + 1], qa[0][kk], kf[cur][p][2], kf[cur][p][3]);
                mma16816(sacc[1][2 * p],     qa[1][kk], kf[cur][p][0], kf[cur][p][1]);
                mma16816(sacc[1][2 * p + 1], qa[1][kk], kf[cur][p][2], kf[cur][p][3]);
                if (kk < 3)
                    ldmx4(kf[cur ^ 1][p],
                          kb + (uint32_t)(p * 16) * KLD + (kk + 1) * 32 + koff);
            }
        }

        // Online softmax per m-tile (max via quad shuffles; l thread-local)
        float al[2][2];
#pragma unroll
        for (int mi = 0; mi < 2; mi++) {
            float mx0 = -1e30f, mx1 = -1e30f;
#pragma unroll
            for (int nt = 0; nt < 8; nt++) {
                mx0 = fmaxf(mx0, fmaxf(sacc[mi][nt][0], sacc[mi][nt][1]));
                mx1 = fmaxf(mx1, fmaxf(sacc[mi][nt][2], sacc[mi][nt][3]));
            }
            mx0 = fmaxf(mx0, __shfl_xor_sync(0xffffffffu, mx0, 1));
            mx0 = fmaxf(mx0, __shfl_xor_sync(0xffffffffu, mx0, 2));
            mx1 = fmaxf(mx1, __shfl_xor_sync(0xffffffffu, mx1, 1));
            mx1 = fmaxf(mx1, __shfl_xor_sync(0xffffffffu, mx1, 2));
            const float mn0 = fmaxf(mrow[mi][0], mx0);
            const float mn1 = fmaxf(mrow[mi][1], mx1);
            al[mi][0] = __expf(mrow[mi][0] - mn0);
            al[mi][1] = __expf(mrow[mi][1] - mn1);
            float s0 = 0.f, s1 = 0.f;
#pragma unroll
            for (int nt = 0; nt < 8; nt++) {
                sacc[mi][nt][0] = __expf(sacc[mi][nt][0] - mn0); s0 += sacc[mi][nt][0];
                sacc[mi][nt][1] = __expf(sacc[mi][nt][1] - mn0); s0 += sacc[mi][nt][1];
                sacc[mi][nt][2] = __expf(sacc[mi][nt][2] - mn1); s1 += sacc[mi][nt][2];
                sacc[mi][nt][3] = __expf(sacc[mi][nt][3] - mn1); s1 += sacc[mi][nt][3];
            }
            lrow[mi][0] = lrow[mi][0] * al[mi][0] + s0;
            lrow[mi][1] = lrow[mi][1] * al[mi][1] + s1;
            mrow[mi][0] = mn0; mrow[mi][1] = mn1;
#pragma unroll
            for (int nt = 0; nt < 8; nt++) {
                oacc[mi][nt][0] *= al[mi][0]; oacc[mi][nt][1] *= al[mi][0];
                oacc[mi][nt][2] *= al[mi][1]; oacc[mi][nt][3] *= al[mi][1];
            }
        }

        // O += P @ V (2 m-tiles share each V fragment)
        uint32_t vf[2][4][4];
#pragma unroll
        for (int p = 0; p < 4; p++)
            ldmx4t(vf[0][p], vb + p * 32 + voff);
#pragma unroll
        for (int kk = 0; kk < 4; kk++) {
            const int cur = kk & 1;
            uint32_t pa[2][4];
#pragma unroll
            for (int mi = 0; mi < 2; mi++) {
                pa[mi][0] = bf2pack(sacc[mi][2 * kk][0],     sacc[mi][2 * kk][1]);
                pa[mi][1] = bf2pack(sacc[mi][2 * kk][2],     sacc[mi][2 * kk][3]);
                pa[mi][2] = bf2pack(sacc[mi][2 * kk + 1][0], sacc[mi][2 * kk + 1][1]);
                pa[mi][3] = bf2pack(sacc[mi][2 * kk + 1][2], sacc[mi][2 * kk + 1][3]);
            }
#pragma unroll
            for (int p = 0; p < 4; p++) {
                mma16816(oacc[0][2 * p],     pa[0], vf[cur][p][0], vf[cur][p][1]);
                mma16816(oacc[0][2 * p + 1], pa[0], vf[cur][p][2], vf[cur][p][3]);
                mma16816(oacc[1][2 * p],     pa[1], vf[cur][p][0], vf[cur][p][1]);
                mma16816(oacc[1][2 * p + 1], pa[1], vf[cur][p][2], vf[cur][p][3]);
                if (kk < 3)
                    ldmx4t(vf[cur ^ 1][p],
                           vb + (uint32_t)((kk + 1) * 16) * KLD + p * 32 + voff);
            }
        }
        if (kt + 3 < TT / 64) issue(kt + 3, (kt + 3) & 3);
        else                  CP_COMMIT();
    }

    // Final l: quad reduce
#pragma unroll
    for (int mi = 0; mi < 2; mi++) {
        lrow[mi][0] += __shfl_xor_sync(0xffffffffu, lrow[mi][0], 1);
        lrow[mi][0] += __shfl_xor_sync(0xffffffffu, lrow[mi][0], 2);
        lrow[mi][1] += __shfl_xor_sync(0xffffffffu, lrow[mi][1], 1);
        lrow[mi][1] += __shfl_xor_sync(0xffffffffu, lrow[mi][1], 2);
    }

    // Epilogue: O / l -> bf16
#pragma unroll
    for (int mi = 0; mi < 2; mi++) {
        const float i0 = 1.f / lrow[mi][0], i1 = 1.f / lrow[mi][1];
        const size_t r0 = (size_t)(b * TT + q0 + warp * 32 + mi * 16 + (lane >> 2)) * DD
                        + h * DKK + (lane & 3) * 2;
        const size_t r1 = r0 + 8 * DD;
#pragma unroll
        for (int nt = 0; nt < 8; nt++) {
            *(uint32_t*)(out + r0 + nt * 8) = bf2pack(oacc[mi][nt][0] * i0,
                                                      oacc[mi][nt][1] * i0);
            *(uint32_t*)(out + r1 + nt * 8) = bf2pack(oacc[mi][nt][2] * i1,
                                                      oacc[mi][nt][3] * i1);
        }
    }
}

// ---------------------------------------------------------------------------
// Fused: res = x + C_raw + b_out ; LayerNorm
// ---------------------------------------------------------------------------
__global__ __launch_bounds__(256)
void ln_fused(const float* __restrict__ Craw, const float* __restrict__ x,
              const float* __restrict__ bout, const float* __restrict__ gamma,
              const float* __restrict__ beta, float* __restrict__ Y)
{
    __shared__ float red[8];
    const int row = blockIdx.x;
    const int tid = threadIdx.x;
    const int c = tid * 4;
    const float4 cv = *(const float4*)(Craw + (size_t)row * DD + c);
    const float4 xv = *(const float4*)(x + (size_t)row * DD + c);
    const float4 bv = *(const float4*)(bout + c);
    float4 v;
    v.x = cv.x + xv.x + bv.x;
    v.y = cv.y + xv.y + bv.y;
    v.z = cv.z + xv.z + bv.z;
    v.w = cv.w + xv.w + bv.w;

    float s = v.x + v.y + v.z + v.w;
#pragma unroll
    for (int off = 16; off >= 1; off >>= 1)
        s += __shfl_xor_sync(0xffffffffu, s, off);
    if ((tid & 31) == 0) red[tid >> 5] = s;
    __syncthreads();
    float tot = red[0] + red[1] + red[2] + red[3] + red[4] + red[5] + red[6] + red[7];
    const float mean = tot * (1.f / 1024.f);
    __syncthreads();

    const float dx = v.x - mean, dy = v.y - mean, dz = v.z - mean, dw = v.w - mean;
    float ss = dx * dx + dy * dy + dz * dz + dw * dw;
#pragma unroll
    for (int off = 16; off >= 1; off >>= 1)
        ss += __shfl_xor_sync(0xffffffffu, ss, off);
    if ((tid & 31) == 0) red[tid >> 5] = ss;
    __syncthreads();
    float var = (red[0] + red[1] + red[2] + red[3] + red[4] + red[5] + red[6] + red[7])
                * (1.f / 1024.f);
    const float rstd = rsqrtf(var + 1e-5f);

    const float4 g = *(const float4*)(gamma + c);
    const float4 be = *(const float4*)(beta + c);
    float4 o;
    o.x = dx * rstd * g.x + be.x;
    o.y = dy * rstd * g.y + be.y;
    o.z = dz * rstd * g.z + be.z;
    o.w = dw * rstd * g.w + be.w;
    *(float4*)(Y + (size_t)row * DD + c) = o;
}

// ---------------------------------------------------------------------------
extern "C" void kernel_launch(void* const* d_in, const int* in_sizes, int n_in,
                              void* d_out, int out_size)
{
    const float* x     = (const float*)d_in[0];
    const float* Wqkv  = (const float*)d_in[1];
    const float* bqkv  = (const float*)d_in[2];
    const float* Wout  = (const float*)d_in[3];
    const float* bout  = (const float*)d_in[4];
    const float* gamma = (const float*)d_in[5];
    const float* beta  = (const float*)d_in[6];
    float* out = (float*)d_out;

    __nv_bfloat16 *xb, *wqkv, *wout, *qkv, *att;
    float* res;
    cudaGetSymbolAddress((void**)&xb, g_xb);
    cudaGetSymbolAddress((void**)&wqkv, g_wqkv);
    cudaGetSymbolAddress((void**)&wout, g_wout);
    cudaGetSymbolAddress((void**)&qkv, g_qkv);
    cudaGetSymbolAddress((void**)&att, g_att);
    cudaGetSymbolAddress((void**)&res, g_res);

    cudaFuncSetAttribute(attn_mma, cudaFuncAttributeMaxDynamicSharedMemorySize, AT_SMEM);
    cudaFuncSetAttribute(gemm_mma<true>, cudaFuncAttributeMaxDynamicSharedMemorySize, GEMM_SMEM);
    cudaFuncSetAttribute(gemm_mma<false>, cudaFuncAttributeMaxDynamicSharedMemorySize, GEMM_SMEM);

    // 0. Prep: convert inputs to bf16
    cvt_bf16_kernel<<<NTOK * DD / 1024, 256>>>(x, xb);
    cvt_bf16_kernel<<<DD * D3 / 1024, 256>>>(Wqkv, wqkv);
    cvt_bf16_kernel<<<DD * DD / 1024, 256>>>(Wout, wout);

    // 1. QKV projection + bias (bf16 out)
    {
        dim3 grid(D3 / 128, NTOK / 128);
        gemm_mma<true><<<grid, 256, GEMM_SMEM>>>(xb, wqkv, bqkv, qkv, NTOK, D3, DD);
    }
    // 2. Attention (4 warps x 32 q/warp, halved K/V LDSM redundancy)
    {
        dim3 grid(TT / 128, BB * HH);
        attn_mma<<<grid, 128, AT_SMEM>>>(qkv, att);
    }
    // 3. Output projection (fp32 out; bias+residual fused into LN)
    {
        dim3 grid(DD / 128, NTOK / 128);
        gemm_mma<false><<<grid, 256, GEMM_SMEM>>>(att, wout, nullptr, res, NTOK, DD, DD);
    }
    // 4. res = x + C + b_out, then LayerNorm
    ln_fused<<<NTOK, 256>>>(res, x, bout, gamma, beta, out);
}